// round 1
// baseline (speedup 1.0000x reference)
#include <cuda_runtime.h>
#include <cuda_bf16.h>

// NCA 3D update step. Shapes fixed by the problem:
//   x:    [4, 64, 64, 64, 16] f32   (B, D, H, W, C)
//   w0:   [128, 64] f32             h = relu(y @ w0^T + b0)
//   b0:   [128] f32
//   w1:   [16, 128] f32             dx = h @ w1^T
//   stoch:[4, 64, 64, 64, 1] f32
// out = (x + dx * (stoch > 0.5)) * (pre_life & alive(x2))

#define SB 4
#define SS 64
#define SC 16
#define SH 128

// scratch (device globals; no allocation allowed)
__device__ float         g_x2[(size_t)SB * SS * SS * SS * SC];   // 64 MB
__device__ float         g_alpha[SB * SS * SS * SS];             // 4 MB
__device__ unsigned char g_pre[SB * SS * SS * SS];               // 1 MB

// ---------------- kernel A: conv + MLP -> x2, alpha, pre_life ----------------
// block: 256 threads = 16x16 (h,w) tile; rolling 3-plane z window in smem.
// smem layout (floats):
//   XS : 16 channels * 3 planes * (18*18)  = 15552   (channel-major)
//   W0 : 128*64 = 8192
//   B0 : 128
//   W1T: 128*16 = 2048  (transposed: [k][j])
#define XS_PLANE 324              // 18*18
#define XS_CH    972              // 3*324
#define SMEM_FLOATS (16*XS_CH + 8192 + 128 + 2048)
#define SMEM_BYTES  (SMEM_FLOATS * 4)

__device__ __forceinline__ void load_plane(float* XS, const float* __restrict__ x,
                                           int b, int zp, int ty0, int tx0,
                                           int slot, int tid) {
    // load one z-plane (with +-1 halo in h,w) of all 16 channels into smem,
    // channel-major. zero-fill out of range (matches SAME zero padding).
    const bool zin = (zp >= 0 && zp < SS);
    for (int i = tid; i < XS_PLANE; i += 256) {
        int hy = i / 18 - 1 + ty0;
        int wx = i % 18 - 1 + tx0;
        int dst = slot * XS_PLANE + i;
        if (zin && hy >= 0 && hy < SS && wx >= 0 && wx < SS) {
            const float4* p = (const float4*)(x + ((((size_t)b * SS + zp) * SS + hy) * SS + wx) * SC);
#pragma unroll
            for (int q = 0; q < 4; q++) {
                float4 v = p[q];
                XS[(4 * q + 0) * XS_CH + dst] = v.x;
                XS[(4 * q + 1) * XS_CH + dst] = v.y;
                XS[(4 * q + 2) * XS_CH + dst] = v.z;
                XS[(4 * q + 3) * XS_CH + dst] = v.w;
            }
        } else {
#pragma unroll
            for (int c = 0; c < 16; c++) XS[c * XS_CH + dst] = 0.f;
        }
    }
}

__global__ __launch_bounds__(256, 2)
void nca_stepA(const float* __restrict__ x, const float* __restrict__ w0,
               const float* __restrict__ b0, const float* __restrict__ w1,
               const float* __restrict__ stoch) {
    extern __shared__ float sm[];
    float* XS  = sm;                   // 15552
    float* W0  = sm + 16 * XS_CH;      // 8192
    float* B0  = W0 + 8192;            // 128
    float* W1T = B0 + 128;             // 2048

    const int tid = threadIdx.x;

    // stage weights
    for (int i = tid; i < 8192 / 4; i += 256)
        ((float4*)W0)[i] = ((const float4*)w0)[i];
    if (tid < 128) B0[tid] = b0[tid];
    for (int i = tid; i < 2048; i += 256) {
        int k = i >> 4, j = i & 15;
        W1T[i] = w1[j * 128 + k];      // W1T[k*16+j] = w1[j][k]
    }

    const int b   = blockIdx.z >> 3;
    const int z0  = (blockIdx.z & 7) * 8;
    const int ty0 = blockIdx.y * 16;
    const int tx0 = blockIdx.x * 16;

    load_plane(XS, x, b, z0 - 1, ty0, tx0, ((z0 - 1) + 3) % 3, tid);
    load_plane(XS, x, b, z0,     ty0, tx0, z0 % 3,             tid);

    const int ly = tid >> 4, lx = tid & 15;
    const int gh = ty0 + ly, gw = tx0 + lx;
    const int cidx = (ly + 1) * 18 + (lx + 1);

    for (int z = z0; z < z0 + 8; z++) {
        load_plane(XS, x, b, z + 1, ty0, tx0, (z + 1) % 3, tid);
        __syncthreads();

        const int sA = ((z - 1) + 3) % 3;   // z-1
        const int sB = z % 3;               // z
        const int sC2 = (z + 1) % 3;        // z+1
        const int slots[3] = { sA, sB, sC2 };

        float y[64];
        float maxa = 0.f;   // alphas in x are >= 0; padded 0s never flip (max>0.1)

#pragma unroll
        for (int c = 0; c < 16; c++) {
            const float* base = XS + c * XS_CH;
            float gx = 0.f, gy = 0.f, gz = 0.f, ctr = 0.f;
#pragma unroll
            for (int dz = 0; dz < 3; dz++) {
                const float wz  = (dz == 1) ? 2.f : 1.f;
                const float dzc = (dz == 0) ? -1.f : (dz == 2 ? 1.f : 0.f);
                const float* pb = base + slots[dz] * XS_PLANE + (cidx - 19);
#pragma unroll
                for (int dy = 0; dy < 3; dy++) {
                    const float wy  = (dy == 1) ? 2.f : 1.f;
                    const float dyc = (dy == 0) ? -1.f : (dy == 2 ? 1.f : 0.f);
#pragma unroll
                    for (int dxx = 0; dxx < 3; dxx++) {
                        const float wx  = (dxx == 1) ? 2.f : 1.f;
                        const float dxc = (dxx == 0) ? -1.f : (dxx == 2 ? 1.f : 0.f);
                        float v = pb[dy * 18 + dxx];
                        if (c == 3) maxa = fmaxf(maxa, v);
                        if (dz == 1 && dy == 1 && dxx == 1) ctr = v;
                        if (dxc != 0.f) gx = fmaf(wz * wy * dxc, v, gx);
                        if (dyc != 0.f) gy = fmaf(wz * wx * dyc, v, gy);
                        if (dzc != 0.f) gz = fmaf(dzc * wy * wx, v, gz);
                    }
                }
            }
            y[c]      = ctr;
            y[16 + c] = gx * (1.f / 32.f);
            y[32 + c] = gy * (1.f / 32.f);
            y[48 + c] = gz * (1.f / 32.f);
        }

        // MLP: h_k = relu(b0[k] + sum_c y[c]*w0[k][c]); dx[j] += h_k * w1[j][k]
        float dxv[16];
#pragma unroll
        for (int j = 0; j < 16; j++) dxv[j] = 0.f;

#pragma unroll 2
        for (int k = 0; k < 128; k++) {
            float acc = B0[k];
            const float* w0p = W0 + k * 64;
#pragma unroll
            for (int c = 0; c < 64; c++) acc = fmaf(y[c], w0p[c], acc);
            acc = fmaxf(acc, 0.f);
            const float* w1p = W1T + k * 16;
#pragma unroll
            for (int j = 0; j < 16; j++) dxv[j] = fmaf(acc, w1p[j], dxv[j]);
        }

        const size_t vox = (((size_t)b * SS + z) * SS + gh) * SS + gw;
        const float m = (stoch[vox] > 0.5f) ? 1.f : 0.f;

        float x2v[16];
#pragma unroll
        for (int j = 0; j < 16; j++) x2v[j] = y[j] + dxv[j] * m;

        float4* o = (float4*)(g_x2 + vox * SC);
#pragma unroll
        for (int q = 0; q < 4; q++)
            o[q] = make_float4(x2v[4 * q], x2v[4 * q + 1], x2v[4 * q + 2], x2v[4 * q + 3]);
        g_alpha[vox] = x2v[3];
        g_pre[vox]   = (maxa > 0.1f) ? 1 : 0;

        __syncthreads();
    }
}

// ---------------- kernel B: alive(x2) maxpool + mask + writeout --------------
__global__ __launch_bounds__(256)
void nca_stepB(float* __restrict__ out) {
    const int v = blockIdx.x * 256 + threadIdx.x;   // 0..1048575
    const int b = v >> 18;
    const int r = v & 262143;
    const int d = r >> 12;
    const int h = (r >> 6) & 63;
    const int w = r & 63;

    float maxa = -1e30f;
#pragma unroll
    for (int dz = -1; dz <= 1; dz++) {
        int dd = d + dz;
        if (dd < 0 || dd >= SS) continue;
#pragma unroll
        for (int dy = -1; dy <= 1; dy++) {
            int hh = h + dy;
            if (hh < 0 || hh >= SS) continue;
#pragma unroll
            for (int dxx = -1; dxx <= 1; dxx++) {
                int ww = w + dxx;
                if (ww < 0 || ww >= SS) continue;
                int idx = (((b * SS + dd) * SS + hh) * SS + ww);
                maxa = fmaxf(maxa, g_alpha[idx]);
            }
        }
    }
    const bool life = (g_pre[v] != 0) && (maxa > 0.1f);
    const float s = life ? 1.f : 0.f;

    const float4* xi = (const float4*)g_x2 + (size_t)v * 4;
    float4* o = (float4*)out + (size_t)v * 4;
#pragma unroll
    for (int q = 0; q < 4; q++) {
        float4 t = xi[q];
        t.x *= s; t.y *= s; t.z *= s; t.w *= s;
        o[q] = t;
    }
}

extern "C" void kernel_launch(void* const* d_in, const int* in_sizes, int n_in,
                              void* d_out, int out_size) {
    const float* x     = (const float*)d_in[0];
    const float* w0    = (const float*)d_in[1];
    const float* b0    = (const float*)d_in[2];
    const float* w1    = (const float*)d_in[3];
    const float* stoch = (const float*)d_in[4];

    cudaFuncSetAttribute(nca_stepA, cudaFuncAttributeMaxDynamicSharedMemorySize, SMEM_BYTES);

    dim3 gridA(4, 4, SB * 8);   // 4 x-tiles, 4 y-tiles, 4 batches * 8 z-chunks
    nca_stepA<<<gridA, 256, SMEM_BYTES>>>(x, w0, b0, w1, stoch);

    const int nvox = SB * SS * SS * SS;  // 1,048,576
    nca_stepB<<<nvox / 256, 256>>>((float*)d_out);
}

// round 3
// speedup vs baseline: 2.5565x; 2.5565x over previous
#include <cuda_runtime.h>
#include <cuda_bf16.h>
#include <cstdint>

// NCA 3D update step — bf16 HMMA (mma.sync) version, sm_103-safe PTX.
//   x:    [4, 64, 64, 64, 16] f32
//   w0:   [128, 64] f32   h = relu(y @ w0^T + b0)
//   b0:   [128] f32
//   w1:   [16, 128] f32   dx = h @ w1^T
//   stoch:[4, 64, 64, 64, 1] f32
// out = (x + dx*(stoch>0.5)) * (pre_life & alive(x2))

#define SB 4
#define SS 64
#define SC 16
#define NVOX (SB * SS * SS * SS)

// ---------------- device scratch ----------------
__device__ __nv_bfloat16 g_y[(size_t)NVOX * 64];     // 128 MB perception vectors
__device__ float         g_x2[(size_t)NVOX * SC];    // 64 MB
__device__ float         g_alpha[NVOX];              // 4 MB
__device__ unsigned char g_pre[NVOX];                // 1 MB
__device__ uint2         g_w0f[64 * 32];             // W0 b-fragments [kt*16+nt][lane]
__device__ uint2         g_w1f[16 * 32];             // W1 b-fragments [kt2*2+nt][lane]

__device__ __forceinline__ uint32_t smem_u32(const void* p) {
    uint32_t a;
    asm("{ .reg .u64 t; cvta.to.shared.u64 t, %1; cvt.u32.u64 %0, t; }" : "=r"(a) : "l"(p));
    return a;
}

__device__ __forceinline__ uint32_t pack_bf16x2(float lo, float hi) {
    uint32_t r;
    asm("cvt.rn.bf16x2.f32 %0, %1, %2;" : "=r"(r) : "f"(hi), "f"(lo));  // d.hi=hi, d.lo=lo
    return r;
}

__device__ __forceinline__ void mma_bf16(float* c, const uint32_t* a, const uint2 b) {
    asm volatile(
        "mma.sync.aligned.m16n8k16.row.col.f32.bf16.bf16.f32 "
        "{%0,%1,%2,%3}, {%4,%5,%6,%7}, {%8,%9}, {%0,%1,%2,%3};"
        : "+f"(c[0]), "+f"(c[1]), "+f"(c[2]), "+f"(c[3])
        : "r"(a[0]), "r"(a[1]), "r"(a[2]), "r"(a[3]), "r"(b.x), "r"(b.y));
}

#define LDMATRIX_X4(r, addr)                                                   \
    asm volatile("ldmatrix.sync.aligned.m8n8.x4.shared.b16 {%0,%1,%2,%3}, [%4];" \
        : "=r"((r)[0]), "=r"((r)[1]), "=r"((r)[2]), "=r"((r)[3]) : "r"(addr))

// ================= prep: pre-shuffle weights into mma fragment order =================
// b-frag for m16n8k16 (B is KxN, B[k][n] = w[n][k]):
//   b.x = {B[2tg][g], B[2tg+1][g]}  (lo = even k)
//   b.y = {B[8+2tg][g], B[9+2tg][g]}
__global__ void nca_prep(const float* __restrict__ w0, const float* __restrict__ w1) {
    for (int t = threadIdx.x; t < 64 * 32 + 16 * 32; t += 256) {
        int lane = t & 31, g = lane >> 2, tg = lane & 3;
        if (t < 64 * 32) {
            int f = t >> 5;                 // 0..63
            int kt = f >> 4, nt = f & 15;   // kt: k16 tile, nt: n8 tile
            int n = nt * 8 + g;
            int kb = kt * 16 + 2 * tg;
            uint2 v;
            v.x = pack_bf16x2(__float2bfloat16_rn(w0[n * 64 + kb]),
                              __float2bfloat16_rn(w0[n * 64 + kb + 1]) ) ;
            // (pack via floats to keep one code path)
            v.x = pack_bf16x2(w0[n * 64 + kb],     w0[n * 64 + kb + 1]);
            v.y = pack_bf16x2(w0[n * 64 + kb + 8], w0[n * 64 + kb + 9]);
            g_w0f[f * 32 + lane] = v;
        } else {
            int f = (t - 64 * 32) >> 5;     // 0..15
            int kt = f >> 1, nt = f & 1;
            int n = nt * 8 + g;
            int kb = kt * 16 + 2 * tg;
            uint2 v;
            v.x = pack_bf16x2(w1[n * 128 + kb],     w1[n * 128 + kb + 1]);
            v.y = pack_bf16x2(w1[n * 128 + kb + 8], w1[n * 128 + kb + 9]);
            g_w1f[f * 32 + lane] = v;
        }
    }
}

// ================= kernel A: conv -> y (bf16), pre_life =================
#define XS_PLANE 324              // 18*18
#define XS_CH    972              // 3*324
#define A_SMEM_BYTES (16 * XS_CH * 4)

__device__ __forceinline__ void load_plane(float* XS, const float* __restrict__ x,
                                           int b, int zp, int ty0, int tx0,
                                           int slot, int tid) {
    const bool zin = (zp >= 0 && zp < SS);
    for (int i = tid; i < XS_PLANE; i += 256) {
        int hy = i / 18 - 1 + ty0;
        int wx = i % 18 - 1 + tx0;
        int dst = slot * XS_PLANE + i;
        if (zin && hy >= 0 && hy < SS && wx >= 0 && wx < SS) {
            const float4* p = (const float4*)(x + ((((size_t)b * SS + zp) * SS + hy) * SS + wx) * SC);
#pragma unroll
            for (int q = 0; q < 4; q++) {
                float4 v = p[q];
                XS[(4 * q + 0) * XS_CH + dst] = v.x;
                XS[(4 * q + 1) * XS_CH + dst] = v.y;
                XS[(4 * q + 2) * XS_CH + dst] = v.z;
                XS[(4 * q + 3) * XS_CH + dst] = v.w;
            }
        } else {
#pragma unroll
            for (int c = 0; c < 16; c++) XS[c * XS_CH + dst] = 0.f;
        }
    }
}

__global__ __launch_bounds__(256, 2)
void nca_conv(const float* __restrict__ x) {
    extern __shared__ float XS[];
    const int tid = threadIdx.x;

    const int b   = blockIdx.z >> 3;
    const int z0  = (blockIdx.z & 7) * 8;
    const int ty0 = blockIdx.y * 16;
    const int tx0 = blockIdx.x * 16;

    load_plane(XS, x, b, z0 - 1, ty0, tx0, ((z0 - 1) + 3) % 3, tid);
    load_plane(XS, x, b, z0,     ty0, tx0, z0 % 3,             tid);

    const int ly = tid >> 4, lx = tid & 15;
    const int gh = ty0 + ly, gw = tx0 + lx;
    const int cidx = (ly + 1) * 18 + (lx + 1);

    for (int z = z0; z < z0 + 8; z++) {
        load_plane(XS, x, b, z + 1, ty0, tx0, (z + 1) % 3, tid);
        __syncthreads();

        const int slots[3] = { ((z - 1) + 3) % 3, z % 3, (z + 1) % 3 };

        float y[64];
        float maxa = 0.f;

#pragma unroll
        for (int c = 0; c < 16; c++) {
            const float* base = XS + c * XS_CH;
            float gx = 0.f, gy = 0.f, gz = 0.f, ctr = 0.f;
#pragma unroll
            for (int dz = 0; dz < 3; dz++) {
                const float wz  = (dz == 1) ? 2.f : 1.f;
                const float dzc = (dz == 0) ? -1.f : (dz == 2 ? 1.f : 0.f);
                const float* pb = base + slots[dz] * XS_PLANE + (cidx - 19);
#pragma unroll
                for (int dy = 0; dy < 3; dy++) {
                    const float wy  = (dy == 1) ? 2.f : 1.f;
                    const float dyc = (dy == 0) ? -1.f : (dy == 2 ? 1.f : 0.f);
#pragma unroll
                    for (int dxx = 0; dxx < 3; dxx++) {
                        const float wx  = (dxx == 1) ? 2.f : 1.f;
                        const float dxc = (dxx == 0) ? -1.f : (dxx == 2 ? 1.f : 0.f);
                        float v = pb[dy * 18 + dxx];
                        if (c == 3) maxa = fmaxf(maxa, v);
                        if (dz == 1 && dy == 1 && dxx == 1) ctr = v;
                        if (dxc != 0.f) gx = fmaf(wz * wy * dxc, v, gx);
                        if (dyc != 0.f) gy = fmaf(wz * wx * dyc, v, gy);
                        if (dzc != 0.f) gz = fmaf(dzc * wy * wx, v, gz);
                    }
                }
            }
            y[c]      = ctr;
            y[16 + c] = gx * (1.f / 32.f);
            y[32 + c] = gy * (1.f / 32.f);
            y[48 + c] = gz * (1.f / 32.f);
        }

        const size_t vox = (((size_t)b * SS + z) * SS + gh) * SS + gw;

        uint32_t packed[32];
#pragma unroll
        for (int i = 0; i < 32; i++) packed[i] = pack_bf16x2(y[2 * i], y[2 * i + 1]);

        uint4* o = (uint4*)(g_y + vox * 64);
#pragma unroll
        for (int q = 0; q < 8; q++)
            o[q] = make_uint4(packed[4 * q], packed[4 * q + 1], packed[4 * q + 2], packed[4 * q + 3]);

        g_pre[vox] = (maxa > 0.1f) ? 1 : 0;
        __syncthreads();
    }
}

// ================= kernel B: double GEMM via mma.sync (bf16) =================
// CTA = 256 threads = 8 warps; 256 voxels per CTA; warp handles 32 voxels (2 m16 tiles).
__global__ __launch_bounds__(256)
void nca_gemm(const float* __restrict__ x, const float* __restrict__ b0,
              const float* __restrict__ stoch) {
    __shared__ __align__(128) uint8_t YS[256 * 128];   // [256 rows][64 bf16], xor-swizzled

    const int tid  = threadIdx.x;
    const int w    = tid >> 5;
    const int lane = tid & 31;
    const int g    = lane >> 2;
    const int tg   = lane & 3;
    const size_t base = (size_t)blockIdx.x * 256;

    // stage Y tile (swizzle: c16 ^= row&7)
    const uint4* ysrc = (const uint4*)g_y + base * 8;
    for (int i = tid; i < 2048; i += 256) {
        int row = i >> 3, c16 = i & 7;
        *(uint4*)(YS + row * 128 + ((c16 ^ (row & 7)) << 4)) = ysrc[i];
    }
    __syncthreads();

    // hoist all A fragments: A[mt][kt][4]
    uint32_t A[2][4][4];
#pragma unroll
    for (int mt = 0; mt < 2; mt++) {
#pragma unroll
        for (int kt = 0; kt < 4; kt++) {
            int r   = w * 32 + mt * 16 + (lane & 15);
            int c16 = kt * 2 + (lane >> 4);
            uint32_t addr = smem_u32(YS) + r * 128 + ((c16 ^ (r & 7)) << 4);
            LDMATRIX_X4(A[mt][kt], addr);
        }
    }

    float dxacc[2][2][4];
#pragma unroll
    for (int i = 0; i < 16; i++) ((float*)dxacc)[i] = 0.f;

#pragma unroll
    for (int nc = 0; nc < 4; nc++) {
        // MMA1 chunk: H cols [nc*32, nc*32+32)
        float hc[2][4][4];
#pragma unroll
        for (int i = 0; i < 32; i++) ((float*)hc)[i] = 0.f;

#pragma unroll
        for (int kt = 0; kt < 4; kt++) {
#pragma unroll
            for (int n8 = 0; n8 < 4; n8++) {
                uint2 b = g_w0f[(kt * 16 + nc * 4 + n8) * 32 + lane];
                mma_bf16(hc[0][n8], A[0][kt], b);
                mma_bf16(hc[1][n8], A[1][kt], b);
            }
        }

        // bias + relu + convert to MMA2 A-fragments
        uint32_t a2[2][2][4];
#pragma unroll
        for (int n8 = 0; n8 < 4; n8++) {
            float bl = b0[nc * 32 + n8 * 8 + 2 * tg];
            float bh = b0[nc * 32 + n8 * 8 + 2 * tg + 1];
            int kt2 = n8 >> 1, half = n8 & 1;
#pragma unroll
            for (int mt = 0; mt < 2; mt++) {
                float f0 = fmaxf(hc[mt][n8][0] + bl, 0.f);
                float f1 = fmaxf(hc[mt][n8][1] + bh, 0.f);
                float f2 = fmaxf(hc[mt][n8][2] + bl, 0.f);
                float f3 = fmaxf(hc[mt][n8][3] + bh, 0.f);
                a2[mt][kt2][half * 2 + 0] = pack_bf16x2(f0, f1);
                a2[mt][kt2][half * 2 + 1] = pack_bf16x2(f2, f3);
            }
        }

        // MMA2: dx += Hchunk * W1chunk^T
#pragma unroll
        for (int kt2 = 0; kt2 < 2; kt2++) {
#pragma unroll
            for (int n8o = 0; n8o < 2; n8o++) {
                uint2 b2 = g_w1f[((nc * 2 + kt2) * 2 + n8o) * 32 + lane];
                mma_bf16(dxacc[0][n8o], a2[0][kt2], b2);
                mma_bf16(dxacc[1][n8o], a2[1][kt2], b2);
            }
        }
    }

    // epilogue: x2 = x + dx*mask ; alpha
#pragma unroll
    for (int mt = 0; mt < 2; mt++) {
        size_t v0 = base + w * 32 + mt * 16 + g;
        size_t v1 = v0 + 8;
        float m0 = (stoch[v0] > 0.5f) ? 1.f : 0.f;
        float m1 = (stoch[v1] > 0.5f) ? 1.f : 0.f;
#pragma unroll
        for (int n8o = 0; n8o < 2; n8o++) {
            int c = n8o * 8 + 2 * tg;
            float2 xv0 = *(const float2*)(x + v0 * 16 + c);
            xv0.x += dxacc[mt][n8o][0] * m0;
            xv0.y += dxacc[mt][n8o][1] * m0;
            *(float2*)(g_x2 + v0 * 16 + c) = xv0;
            float2 xv1 = *(const float2*)(x + v1 * 16 + c);
            xv1.x += dxacc[mt][n8o][2] * m1;
            xv1.y += dxacc[mt][n8o][3] * m1;
            *(float2*)(g_x2 + v1 * 16 + c) = xv1;
            if (n8o == 0 && tg == 1) {   // col pair (2,3): .y is alpha (ch 3)
                g_alpha[v0] = xv0.y;
                g_alpha[v1] = xv1.y;
            }
        }
    }
}

// ================= kernel C: alive(x2) maxpool + mask + writeout =================
__global__ __launch_bounds__(256)
void nca_stepB(float* __restrict__ out) {
    const int v = blockIdx.x * 256 + threadIdx.x;
    const int b = v >> 18;
    const int r = v & 262143;
    const int d = r >> 12;
    const int h = (r >> 6) & 63;
    const int w = r & 63;

    float maxa = -1e30f;
#pragma unroll
    for (int dz = -1; dz <= 1; dz++) {
        int dd = d + dz;
        if (dd < 0 || dd >= SS) continue;
#pragma unroll
        for (int dy = -1; dy <= 1; dy++) {
            int hh = h + dy;
            if (hh < 0 || hh >= SS) continue;
#pragma unroll
            for (int dxx = -1; dxx <= 1; dxx++) {
                int ww = w + dxx;
                if (ww < 0 || ww >= SS) continue;
                maxa = fmaxf(maxa, g_alpha[(((b * SS + dd) * SS + hh) * SS + ww)]);
            }
        }
    }
    const bool life = (g_pre[v] != 0) && (maxa > 0.1f);
    const float s = life ? 1.f : 0.f;

    const float4* xi = (const float4*)g_x2 + (size_t)v * 4;
    float4* o = (float4*)out + (size_t)v * 4;
#pragma unroll
    for (int q = 0; q < 4; q++) {
        float4 t = xi[q];
        t.x *= s; t.y *= s; t.z *= s; t.w *= s;
        o[q] = t;
    }
}

extern "C" void kernel_launch(void* const* d_in, const int* in_sizes, int n_in,
                              void* d_out, int out_size) {
    const float* x     = (const float*)d_in[0];
    const float* w0    = (const float*)d_in[1];
    const float* b0    = (const float*)d_in[2];
    const float* w1    = (const float*)d_in[3];
    const float* stoch = (const float*)d_in[4];

    nca_prep<<<1, 256>>>(w0, w1);

    cudaFuncSetAttribute(nca_conv, cudaFuncAttributeMaxDynamicSharedMemorySize, A_SMEM_BYTES);
    dim3 gridA(4, 4, SB * 8);
    nca_conv<<<gridA, 256, A_SMEM_BYTES>>>(x);

    nca_gemm<<<NVOX / 256, 256>>>(x, b0, stoch);

    nca_stepB<<<NVOX / 256, 256>>>((float*)d_out);
}

// round 4
// speedup vs baseline: 3.0090x; 1.1770x over previous
#include <cuda_runtime.h>
#include <cuda_bf16.h>
#include <cstdint>

// NCA 3D update step — bf16 HMMA, separable conv with x-blocking.
//   x:[4,64,64,64,16] f32, w0:[128,64], b0:[128], w1:[16,128], stoch:[4,64^3,1]
// out = (x + dx*(stoch>0.5)) * (pre_life & alive(x2))
//
// y is stored K-PERMUTED: y'[vox][4c+s] = {x_c, gx_c, gy_c, gz_c}, gradients
// pre-normalization (the 1/32 is folded into the W0 fragments).

#define SB 4
#define SS 64
#define SC 16
#define NVOX (SB * SS * SS * SS)

// ---------------- device scratch ----------------
__device__ __nv_bfloat16 g_y[(size_t)NVOX * 64];     // 128 MB (permuted K)
__device__ float         g_x2[(size_t)NVOX * SC];    // 64 MB
__device__ float         g_alpha[NVOX];              // 4 MB
__device__ unsigned char g_pre[NVOX];                // 1 MB
__device__ uint2         g_w0f[64 * 32];             // W0 b-frags (permuted K, scaled)
__device__ uint2         g_w1f[16 * 32];             // W1 b-frags

__device__ __forceinline__ uint32_t smem_u32(const void* p) {
    uint32_t a;
    asm("{ .reg .u64 t; cvta.to.shared.u64 t, %1; cvt.u32.u64 %0, t; }" : "=r"(a) : "l"(p));
    return a;
}
__device__ __forceinline__ uint32_t pack_bf16x2(float lo, float hi) {
    uint32_t r;
    asm("cvt.rn.bf16x2.f32 %0, %1, %2;" : "=r"(r) : "f"(hi), "f"(lo));
    return r;
}
__device__ __forceinline__ void mma_bf16(float* c, const uint32_t* a, const uint2 b) {
    asm volatile(
        "mma.sync.aligned.m16n8k16.row.col.f32.bf16.bf16.f32 "
        "{%0,%1,%2,%3}, {%4,%5,%6,%7}, {%8,%9}, {%0,%1,%2,%3};"
        : "+f"(c[0]), "+f"(c[1]), "+f"(c[2]), "+f"(c[3])
        : "r"(a[0]), "r"(a[1]), "r"(a[2]), "r"(a[3]), "r"(b.x), "r"(b.y));
}
#define LDMATRIX_X4(r, addr)                                                   \
    asm volatile("ldmatrix.sync.aligned.m8n8.x4.shared.b16 {%0,%1,%2,%3}, [%4];" \
        : "=r"((r)[0]), "=r"((r)[1]), "=r"((r)[2]), "=r"((r)[3]) : "r"(addr))

// ================= prep: weights -> mma b-fragments =================
// K-permutation: y'[k'] = y_orig[orig(k')], orig(k') = (k'&3)*16 + (k'>>2).
// Gradient rows (orig>=16) absorb the 1/32 normalization.
__global__ void nca_prep(const float* __restrict__ w0, const float* __restrict__ w1) {
    for (int t = threadIdx.x; t < 64 * 32 + 16 * 32; t += 256) {
        int lane = t & 31, g = lane >> 2, tg = lane & 3;
        if (t < 64 * 32) {
            int f = t >> 5;                 // 0..63
            int kt = f >> 4, nt = f & 15;
            int n = nt * 8 + g;
            int kb = kt * 16 + 2 * tg;
            float e[4];
#pragma unroll
            for (int q = 0; q < 4; q++) {
                int kp = kb + (q >> 1) * 8 + (q & 1);      // k', k'+1, k'+8, k'+9
                int ko = (kp & 3) * 16 + (kp >> 2);        // original K index
                float s = (ko >= 16) ? (1.f / 32.f) : 1.f;
                e[q] = w0[n * 64 + ko] * s;
            }
            uint2 v;
            v.x = pack_bf16x2(e[0], e[1]);
            v.y = pack_bf16x2(e[2], e[3]);
            g_w0f[f * 32 + lane] = v;
        } else {
            int f = (t - 64 * 32) >> 5;     // 0..15
            int kt = f >> 1, nt = f & 1;
            int n = nt * 8 + g;
            int kb = kt * 16 + 2 * tg;
            uint2 v;
            v.x = pack_bf16x2(w1[n * 128 + kb],     w1[n * 128 + kb + 1]);
            v.y = pack_bf16x2(w1[n * 128 + kb + 8], w1[n * 128 + kb + 9]);
            g_w1f[f * 32 + lane] = v;
        }
    }
}

// ================= kernel A: separable conv -> y' (bf16), pre_life =================
// plane: 18 halo rows x 19 (padded) cols. 3-plane rolling z window, channel-major.
#define XROW 19
#define XS_PLANE (18 * XROW)      // 342
#define XS_CH    (3 * XS_PLANE)   // 1026
#define A_SMEM_BYTES (16 * XS_CH * 4)

__device__ __forceinline__ void load_plane(float* XS, const float* __restrict__ x,
                                           int b, int zp, int ty0, int tx0,
                                           int slot, int tid) {
    const bool zin = (zp >= 0 && zp < SS);
    for (int i = tid; i < 18 * 18; i += 256) {
        int hy = i / 18;
        int wx = i % 18;
        int dst = slot * XS_PLANE + hy * XROW + wx;
        int gy2 = hy - 1 + ty0, gx2 = wx - 1 + tx0;
        if (zin && gy2 >= 0 && gy2 < SS && gx2 >= 0 && gx2 < SS) {
            const float4* p = (const float4*)(x + ((((size_t)b * SS + zp) * SS + gy2) * SS + gx2) * SC);
#pragma unroll
            for (int q = 0; q < 4; q++) {
                float4 v = p[q];
                XS[(4 * q + 0) * XS_CH + dst] = v.x;
                XS[(4 * q + 1) * XS_CH + dst] = v.y;
                XS[(4 * q + 2) * XS_CH + dst] = v.z;
                XS[(4 * q + 3) * XS_CH + dst] = v.w;
            }
        } else {
#pragma unroll
            for (int c = 0; c < 16; c++) XS[c * XS_CH + dst] = 0.f;
        }
    }
}

__global__ __launch_bounds__(256, 2)
void nca_conv(const float* __restrict__ x) {
    extern __shared__ float XS[];
    const int tid = threadIdx.x;

    const int b   = blockIdx.z >> 3;
    const int z0  = (blockIdx.z & 7) * 8;
    const int ty0 = blockIdx.y * 16;
    const int tx0 = blockIdx.x * 16;

    load_plane(XS, x, b, z0 - 1, ty0, tx0, ((z0 - 1) + 3) % 3, tid);
    load_plane(XS, x, b, z0,     ty0, tx0, z0 % 3,             tid);

    // thread -> (cg: 4 channels, ly: row, tx4: 4 x-voxels)
    const int cg  = tid >> 6;          // 0..3
    const int sub = tid & 63;
    const int ly  = sub >> 2;          // 0..15
    const int tx4 = sub & 3;           // 0..3
    const int gh  = ty0 + ly;
    const int gx0 = tx0 + 4 * tx4;

    for (int z = z0; z < z0 + 8; z++) {
        load_plane(XS, x, b, z + 1, ty0, tx0, (z + 1) % 3, tid);
        __syncthreads();

        const int s0 = ((z - 1) + 3) % 3, s1 = z % 3, s2 = (z + 1) % 3;
        const size_t voxbase = (((size_t)b * SS + z) * SS + gh) * SS + gx0;

#pragma unroll
        for (int cpair = 0; cpair < 2; cpair++) {
            float st[2][4][4];   // [ci][vox][{ctr,gx,gy,gz}]
#pragma unroll
            for (int ci = 0; ci < 2; ci++) {
                const int c = cg * 4 + cpair * 2 + ci;
                const float* base = XS + c * XS_CH;

                float a[3][6], d[3][6], ctrv[4], cm[6];
#pragma unroll
                for (int dy = 0; dy < 3; dy++) {
#pragma unroll
                    for (int j = 0; j < 6; j++) {
                        int idx = (ly + dy) * XROW + 4 * tx4 + j;
                        float vm = base[s0 * XS_PLANE + idx];
                        float vc = base[s1 * XS_PLANE + idx];
                        float vp = base[s2 * XS_PLANE + idx];
                        a[dy][j] = fmaf(2.f, vc, vm) + vp;
                        d[dy][j] = vp - vm;
                        if (c == 3) {
                            float m = fmaxf(fmaxf(vm, vc), vp);
                            cm[j] = (dy == 0) ? m : fmaxf(cm[j], m);
                        }
                        if (dy == 1 && j >= 1 && j <= 4) ctrv[j - 1] = vc;
                    }
                }
#pragma unroll
                for (int v = 0; v < 4; v++) {
                    float gx = (a[0][v + 2] - a[0][v])
                             + 2.f * (a[1][v + 2] - a[1][v])
                             + (a[2][v + 2] - a[2][v]);
                    float sx0 = fmaf(2.f, a[0][v + 1], a[0][v]) + a[0][v + 2];
                    float sx2 = fmaf(2.f, a[2][v + 1], a[2][v]) + a[2][v + 2];
                    float gy = sx2 - sx0;
                    float t0 = fmaf(2.f, d[0][v + 1], d[0][v]) + d[0][v + 2];
                    float t1 = fmaf(2.f, d[1][v + 1], d[1][v]) + d[1][v + 2];
                    float t2 = fmaf(2.f, d[2][v + 1], d[2][v]) + d[2][v + 2];
                    float gz = fmaf(2.f, t1, t0) + t2;
                    st[ci][v][0] = ctrv[v];
                    st[ci][v][1] = gx;
                    st[ci][v][2] = gy;
                    st[ci][v][3] = gz;
                }
                if (c == 3) {
                    uchar4 pre;
                    pre.x = (fmaxf(fmaxf(cm[0], cm[1]), cm[2]) > 0.1f) ? 1 : 0;
                    pre.y = (fmaxf(fmaxf(cm[1], cm[2]), cm[3]) > 0.1f) ? 1 : 0;
                    pre.z = (fmaxf(fmaxf(cm[2], cm[3]), cm[4]) > 0.1f) ? 1 : 0;
                    pre.w = (fmaxf(fmaxf(cm[3], cm[4]), cm[5]) > 0.1f) ? 1 : 0;
                    *(uchar4*)(g_pre + voxbase) = pre;
                }
            }
            // write: y'[vox][4c..4c+8) for c = cg*4 + cpair*2 (8 bf16 = 16B)
            const int eoff = (cg * 4 + cpair * 2) * 4;   // element offset in y' row
#pragma unroll
            for (int v = 0; v < 4; v++) {
                uint4 o;
                o.x = pack_bf16x2(st[0][v][0], st[0][v][1]);
                o.y = pack_bf16x2(st[0][v][2], st[0][v][3]);
                o.z = pack_bf16x2(st[1][v][0], st[1][v][1]);
                o.w = pack_bf16x2(st[1][v][2], st[1][v][3]);
                *(uint4*)(g_y + (voxbase + v) * 64 + eoff) = o;
            }
        }
        __syncthreads();
    }
}

// ================= kernel B: double GEMM via mma.sync (bf16) =================
__global__ __launch_bounds__(256)
void nca_gemm(const float* __restrict__ x, const float* __restrict__ b0,
              const float* __restrict__ stoch) {
    __shared__ __align__(128) uint8_t YS[256 * 128];   // 32KB, xor-swizzled
    __shared__ __align__(16) uint2 W0F[64 * 32];       // 16KB
    __shared__ __align__(16) uint2 W1F[16 * 32];       // 4KB
    __shared__ float B0S[128];

    const int tid  = threadIdx.x;
    const int w    = tid >> 5;
    const int lane = tid & 31;
    const int g    = lane >> 2;
    const int tg   = lane & 3;
    const size_t base = (size_t)blockIdx.x * 256;

    // stage weights (uint4 copies) + bias
    {
        const uint4* s0 = (const uint4*)g_w0f;
        uint4* d0 = (uint4*)W0F;
        for (int i = tid; i < 1024; i += 256) d0[i] = s0[i];
        const uint4* s1 = (const uint4*)g_w1f;
        uint4* d1 = (uint4*)W1F;
        if (tid < 256) d1[tid] = s1[tid];
        if (tid < 128) B0S[tid] = b0[tid];
    }
    // stage Y tile (swizzle: c16 ^= row&7)
    const uint4* ysrc = (const uint4*)g_y + base * 8;
    for (int i = tid; i < 2048; i += 256) {
        int row = i >> 3, c16 = i & 7;
        *(uint4*)(YS + row * 128 + ((c16 ^ (row & 7)) << 4)) = ysrc[i];
    }
    __syncthreads();

    // hoist all A fragments
    uint32_t A[2][4][4];
#pragma unroll
    for (int mt = 0; mt < 2; mt++) {
#pragma unroll
        for (int kt = 0; kt < 4; kt++) {
            int r   = w * 32 + mt * 16 + (lane & 15);
            int c16 = kt * 2 + (lane >> 4);
            uint32_t addr = smem_u32(YS) + r * 128 + ((c16 ^ (r & 7)) << 4);
            LDMATRIX_X4(A[mt][kt], addr);
        }
    }

    float dxacc[2][2][4];
#pragma unroll
    for (int i = 0; i < 16; i++) ((float*)dxacc)[i] = 0.f;

#pragma unroll
    for (int nc = 0; nc < 4; nc++) {
        float hc[2][4][4];
#pragma unroll
        for (int i = 0; i < 32; i++) ((float*)hc)[i] = 0.f;

#pragma unroll
        for (int kt = 0; kt < 4; kt++) {
#pragma unroll
            for (int n8 = 0; n8 < 4; n8++) {
                uint2 b = W0F[(kt * 16 + nc * 4 + n8) * 32 + lane];
                mma_bf16(hc[0][n8], A[0][kt], b);
                mma_bf16(hc[1][n8], A[1][kt], b);
            }
        }

        uint32_t a2[2][2][4];
#pragma unroll
        for (int n8 = 0; n8 < 4; n8++) {
            float2 bb = *(const float2*)(B0S + nc * 32 + n8 * 8 + 2 * tg);
            int kt2 = n8 >> 1, half = n8 & 1;
#pragma unroll
            for (int mt = 0; mt < 2; mt++) {
                float f0 = fmaxf(hc[mt][n8][0] + bb.x, 0.f);
                float f1 = fmaxf(hc[mt][n8][1] + bb.y, 0.f);
                float f2 = fmaxf(hc[mt][n8][2] + bb.x, 0.f);
                float f3 = fmaxf(hc[mt][n8][3] + bb.y, 0.f);
                a2[mt][kt2][half * 2 + 0] = pack_bf16x2(f0, f1);
                a2[mt][kt2][half * 2 + 1] = pack_bf16x2(f2, f3);
            }
        }

#pragma unroll
        for (int kt2 = 0; kt2 < 2; kt2++) {
#pragma unroll
            for (int n8o = 0; n8o < 2; n8o++) {
                uint2 b2 = W1F[((nc * 2 + kt2) * 2 + n8o) * 32 + lane];
                mma_bf16(dxacc[0][n8o], a2[0][kt2], b2);
                mma_bf16(dxacc[1][n8o], a2[1][kt2], b2);
            }
        }
    }

    // epilogue: x2 = x + dx*mask ; alpha
#pragma unroll
    for (int mt = 0; mt < 2; mt++) {
        size_t v0 = base + w * 32 + mt * 16 + g;
        size_t v1 = v0 + 8;
        float m0 = (stoch[v0] > 0.5f) ? 1.f : 0.f;
        float m1 = (stoch[v1] > 0.5f) ? 1.f : 0.f;
#pragma unroll
        for (int n8o = 0; n8o < 2; n8o++) {
            int c = n8o * 8 + 2 * tg;
            float2 xv0 = *(const float2*)(x + v0 * 16 + c);
            xv0.x += dxacc[mt][n8o][0] * m0;
            xv0.y += dxacc[mt][n8o][1] * m0;
            *(float2*)(g_x2 + v0 * 16 + c) = xv0;
            float2 xv1 = *(const float2*)(x + v1 * 16 + c);
            xv1.x += dxacc[mt][n8o][2] * m1;
            xv1.y += dxacc[mt][n8o][3] * m1;
            *(float2*)(g_x2 + v1 * 16 + c) = xv1;
            if (n8o == 0 && tg == 1) {
                g_alpha[v0] = xv0.y;
                g_alpha[v1] = xv1.y;
            }
        }
    }
}

// ================= kernel C: alive(x2) maxpool + mask + writeout =================
__global__ __launch_bounds__(256)
void nca_stepB(float* __restrict__ out) {
    const int v = blockIdx.x * 256 + threadIdx.x;
    const int b = v >> 18;
    const int r = v & 262143;
    const int d = r >> 12;
    const int h = (r >> 6) & 63;
    const int w = r & 63;

    float maxa = -1e30f;
#pragma unroll
    for (int dz = -1; dz <= 1; dz++) {
        int dd = d + dz;
        if (dd < 0 || dd >= SS) continue;
#pragma unroll
        for (int dy = -1; dy <= 1; dy++) {
            int hh = h + dy;
            if (hh < 0 || hh >= SS) continue;
#pragma unroll
            for (int dxx = -1; dxx <= 1; dxx++) {
                int ww = w + dxx;
                if (ww < 0 || ww >= SS) continue;
                maxa = fmaxf(maxa, g_alpha[(((b * SS + dd) * SS + hh) * SS + ww)]);
            }
        }
    }
    const bool life = (g_pre[v] != 0) && (maxa > 0.1f);
    const float s = life ? 1.f : 0.f;

    const float4* xi = (const float4*)g_x2 + (size_t)v * 4;
    float4* o = (float4*)out + (size_t)v * 4;
#pragma unroll
    for (int q = 0; q < 4; q++) {
        float4 t = xi[q];
        t.x *= s; t.y *= s; t.z *= s; t.w *= s;
        o[q] = t;
    }
}

extern "C" void kernel_launch(void* const* d_in, const int* in_sizes, int n_in,
                              void* d_out, int out_size) {
    const float* x     = (const float*)d_in[0];
    const float* w0    = (const float*)d_in[1];
    const float* b0    = (const float*)d_in[2];
    const float* w1    = (const float*)d_in[3];
    const float* stoch = (const float*)d_in[4];

    nca_prep<<<1, 256>>>(w0, w1);

    cudaFuncSetAttribute(nca_conv, cudaFuncAttributeMaxDynamicSharedMemorySize, A_SMEM_BYTES);
    dim3 gridA(4, 4, SB * 8);
    nca_conv<<<gridA, 256, A_SMEM_BYTES>>>(x);

    nca_gemm<<<NVOX / 256, 256>>>(x, b0, stoch);

    nca_stepB<<<NVOX / 256, 256>>>((float*)d_out);
}

// round 5
// speedup vs baseline: 4.3309x; 1.4393x over previous
#include <cuda_runtime.h>
#include <cuda_bf16.h>
#include <cstdint>

// NCA 3D update step — fused conv+GEMM (bf16 HMMA), no intermediate y buffer.
//   x:[4,64,64,64,16] f32, w0:[128,64], b0:[128], w1:[16,128], stoch:[4,64^3,1]
// out = (x + dx*(stoch>0.5)) * (pre_life & alive(x2))
// y is K-PERMUTED in YS smem: y'[4c+s] = {x_c, gx_c, gy_c, gz_c}; 1/32 folded into W0.

#define SB 4
#define SS 64
#define SC 16
#define NVOX (SB * SS * SS * SS)

// ---------------- device scratch ----------------
__device__ float         g_x2[(size_t)NVOX * SC];    // 64 MB
__device__ float         g_alpha[NVOX];              // 4 MB
__device__ unsigned char g_pre[NVOX];                // 1 MB
__device__ uint2         g_w0f[64 * 32];             // W0 b-frags (permuted K, scaled)
__device__ uint2         g_w1f[16 * 32];             // W1 b-frags

__device__ __forceinline__ uint32_t smem_u32(const void* p) {
    uint32_t a;
    asm("{ .reg .u64 t; cvta.to.shared.u64 t, %1; cvt.u32.u64 %0, t; }" : "=r"(a) : "l"(p));
    return a;
}
__device__ __forceinline__ uint32_t pack_bf16x2(float lo, float hi) {
    uint32_t r;
    asm("cvt.rn.bf16x2.f32 %0, %1, %2;" : "=r"(r) : "f"(hi), "f"(lo));
    return r;
}
__device__ __forceinline__ void mma_bf16(float* c, const uint32_t* a, const uint2 b) {
    asm volatile(
        "mma.sync.aligned.m16n8k16.row.col.f32.bf16.bf16.f32 "
        "{%0,%1,%2,%3}, {%4,%5,%6,%7}, {%8,%9}, {%0,%1,%2,%3};"
        : "+f"(c[0]), "+f"(c[1]), "+f"(c[2]), "+f"(c[3])
        : "r"(a[0]), "r"(a[1]), "r"(a[2]), "r"(a[3]), "r"(b.x), "r"(b.y));
}
#define LDMATRIX_X4(r, addr)                                                   \
    asm volatile("ldmatrix.sync.aligned.m8n8.x4.shared.b16 {%0,%1,%2,%3}, [%4];" \
        : "=r"((r)[0]), "=r"((r)[1]), "=r"((r)[2]), "=r"((r)[3]) : "r"(addr))

// ================= prep: weights -> mma b-fragments (K-permuted, scaled) =====
__global__ void nca_prep(const float* __restrict__ w0, const float* __restrict__ w1) {
    for (int t = threadIdx.x; t < 64 * 32 + 16 * 32; t += 256) {
        int lane = t & 31, g = lane >> 2, tg = lane & 3;
        if (t < 64 * 32) {
            int f = t >> 5;
            int kt = f >> 4, nt = f & 15;
            int n = nt * 8 + g;
            int kb = kt * 16 + 2 * tg;
            float e[4];
#pragma unroll
            for (int q = 0; q < 4; q++) {
                int kp = kb + (q >> 1) * 8 + (q & 1);
                int ko = (kp & 3) * 16 + (kp >> 2);
                float s = (ko >= 16) ? (1.f / 32.f) : 1.f;
                e[q] = w0[n * 64 + ko] * s;
            }
            uint2 v;
            v.x = pack_bf16x2(e[0], e[1]);
            v.y = pack_bf16x2(e[2], e[3]);
            g_w0f[f * 32 + lane] = v;
        } else {
            int f = (t - 64 * 32) >> 5;
            int kt = f >> 1, nt = f & 1;
            int n = nt * 8 + g;
            int kb = kt * 16 + 2 * tg;
            uint2 v;
            v.x = pack_bf16x2(w1[n * 128 + kb],     w1[n * 128 + kb + 1]);
            v.y = pack_bf16x2(w1[n * 128 + kb + 8], w1[n * 128 + kb + 9]);
            g_w1f[f * 32 + lane] = v;
        }
    }
}

// ================= fused kernel: conv -> YS(smem) -> double GEMM -> x2 =======
// CTA: 512 threads, 16x32 (h,w) tile, 4 z-slices, rolling 3-plane window.
#define TY 16
#define TX 32
#define TZ 4
#define XROW 35                   // 34 used + 1 pad
#define XS_PLANE (18 * XROW)      // 630
#define XS_CH    (3 * XS_PLANE)   // 1890
#define XS_BYTES (16 * XS_CH * 4) // 120960
#define YS_BYTES (512 * 128)      // 65536
#define F_SMEM_BYTES (XS_BYTES + YS_BYTES + 16384 + 4096 + 512)

__device__ __forceinline__ void load_plane(float* XS, const float* __restrict__ x,
                                           int b, int zp, int ty0, int tx0,
                                           int slot, int tid) {
    const bool zin = (zp >= 0 && zp < SS);
    for (int i = tid; i < 18 * 34; i += 512) {
        int hy = i / 34;
        int wx = i % 34;
        int dst = slot * XS_PLANE + hy * XROW + wx;
        int gy2 = hy - 1 + ty0, gx2 = wx - 1 + tx0;
        if (zin && gy2 >= 0 && gy2 < SS && gx2 >= 0 && gx2 < SS) {
            const float4* p = (const float4*)(x + ((((size_t)b * SS + zp) * SS + gy2) * SS + gx2) * SC);
#pragma unroll
            for (int q = 0; q < 4; q++) {
                float4 v = p[q];
                XS[(4 * q + 0) * XS_CH + dst] = v.x;
                XS[(4 * q + 1) * XS_CH + dst] = v.y;
                XS[(4 * q + 2) * XS_CH + dst] = v.z;
                XS[(4 * q + 3) * XS_CH + dst] = v.w;
            }
        } else {
#pragma unroll
            for (int c = 0; c < 16; c++) XS[c * XS_CH + dst] = 0.f;
        }
    }
}

__global__ __launch_bounds__(512, 1)
void nca_fused(const float* __restrict__ x, const float* __restrict__ b0,
               const float* __restrict__ stoch) {
    extern __shared__ float SM[];
    float*   XS  = SM;
    uint8_t* YS  = (uint8_t*)(SM + 16 * XS_CH);
    uint2*   W0F = (uint2*)(YS + YS_BYTES);
    uint2*   W1F = W0F + 64 * 32;
    float*   B0S = (float*)(W1F + 16 * 32);

    const int tid = threadIdx.x;

    // stage weights once per CTA
    {
        const uint4* s0 = (const uint4*)g_w0f;
        uint4* d0 = (uint4*)W0F;
        for (int i = tid; i < 1024; i += 512) d0[i] = s0[i];
        if (tid < 256) ((uint4*)W1F)[tid] = ((const uint4*)g_w1f)[tid];
        if (tid < 128) B0S[tid] = b0[tid];
    }

    const int b   = blockIdx.z >> 4;
    const int z0  = (blockIdx.z & 15) * TZ;
    const int ty0 = blockIdx.y * TY;
    const int tx0 = blockIdx.x * TX;

    load_plane(XS, x, b, z0 - 1, ty0, tx0, ((z0 - 1) + 3) % 3, tid);
    load_plane(XS, x, b, z0,     ty0, tx0, z0 % 3,             tid);

    // conv mapping: cg(4 channels) x ly(16) x tx4(8 groups of 4 x-voxels)
    const int cg  = tid >> 7;
    const int sub = tid & 127;
    const int ly  = sub >> 3;
    const int tx4 = sub & 7;
    const int gh  = ty0 + ly;
    const int gx0 = tx0 + 4 * tx4;

    // gemm mapping
    const int w    = tid >> 5;
    const int lane = tid & 31;
    const int g    = lane >> 2;
    const int tg   = lane & 3;

    for (int z = z0; z < z0 + TZ; z++) {
        load_plane(XS, x, b, z + 1, ty0, tx0, (z + 1) % 3, tid);
        __syncthreads();

        const int s0 = ((z - 1) + 3) % 3, s1 = z % 3, s2 = (z + 1) % 3;
        const size_t voxbase = (((size_t)b * SS + z) * SS + gh) * SS + gx0;
        const int lrow0 = ly * TX + 4 * tx4;   // local voxel row in YS

        // ---------------- conv phase: y' -> YS ----------------
#pragma unroll
        for (int cpair = 0; cpair < 2; cpair++) {
            float st[2][4][4];
#pragma unroll
            for (int ci = 0; ci < 2; ci++) {
                const int c = cg * 4 + cpair * 2 + ci;
                const float* base = XS + c * XS_CH;

                float a[3][6], d[3][6], ctrv[4], cm[6];
#pragma unroll
                for (int dy = 0; dy < 3; dy++) {
#pragma unroll
                    for (int j = 0; j < 6; j++) {
                        int idx = (ly + dy) * XROW + 4 * tx4 + j;
                        float vm = base[s0 * XS_PLANE + idx];
                        float vc = base[s1 * XS_PLANE + idx];
                        float vp = base[s2 * XS_PLANE + idx];
                        a[dy][j] = fmaf(2.f, vc, vm) + vp;
                        d[dy][j] = vp - vm;
                        if (c == 3) {
                            float m = fmaxf(fmaxf(vm, vc), vp);
                            cm[j] = (dy == 0) ? m : fmaxf(cm[j], m);
                        }
                        if (dy == 1 && j >= 1 && j <= 4) ctrv[j - 1] = vc;
                    }
                }
#pragma unroll
                for (int v = 0; v < 4; v++) {
                    float gx = (a[0][v + 2] - a[0][v])
                             + 2.f * (a[1][v + 2] - a[1][v])
                             + (a[2][v + 2] - a[2][v]);
                    float sx0 = fmaf(2.f, a[0][v + 1], a[0][v]) + a[0][v + 2];
                    float sx2 = fmaf(2.f, a[2][v + 1], a[2][v]) + a[2][v + 2];
                    float gy = sx2 - sx0;
                    float t0 = fmaf(2.f, d[0][v + 1], d[0][v]) + d[0][v + 2];
                    float t1 = fmaf(2.f, d[1][v + 1], d[1][v]) + d[1][v + 2];
                    float t2 = fmaf(2.f, d[2][v + 1], d[2][v]) + d[2][v + 2];
                    float gz = fmaf(2.f, t1, t0) + t2;
                    st[ci][v][0] = ctrv[v];
                    st[ci][v][1] = gx;
                    st[ci][v][2] = gy;
                    st[ci][v][3] = gz;
                }
                if (c == 3) {
                    uchar4 pre;
                    pre.x = (fmaxf(fmaxf(cm[0], cm[1]), cm[2]) > 0.1f) ? 1 : 0;
                    pre.y = (fmaxf(fmaxf(cm[1], cm[2]), cm[3]) > 0.1f) ? 1 : 0;
                    pre.z = (fmaxf(fmaxf(cm[2], cm[3]), cm[4]) > 0.1f) ? 1 : 0;
                    pre.w = (fmaxf(fmaxf(cm[3], cm[4]), cm[5]) > 0.1f) ? 1 : 0;
                    *(uchar4*)(g_pre + voxbase) = pre;
                }
            }
            // write y' to YS smem, xor-swizzled (c16 ^= row&7)
            const int c16 = cg * 2 + cpair;
#pragma unroll
            for (int v = 0; v < 4; v++) {
                int row = lrow0 + v;
                uint4 o;
                o.x = pack_bf16x2(st[0][v][0], st[0][v][1]);
                o.y = pack_bf16x2(st[0][v][2], st[0][v][3]);
                o.z = pack_bf16x2(st[1][v][0], st[1][v][1]);
                o.w = pack_bf16x2(st[1][v][2], st[1][v][3]);
                *(uint4*)(YS + row * 128 + ((c16 ^ (row & 7)) << 4)) = o;
            }
        }
        __syncthreads();

        // ---------------- GEMM phase ----------------
        uint32_t A[2][4][4];
#pragma unroll
        for (int mt = 0; mt < 2; mt++) {
#pragma unroll
            for (int kt = 0; kt < 4; kt++) {
                int r   = w * 32 + mt * 16 + (lane & 15);
                int c16 = kt * 2 + (lane >> 4);
                uint32_t addr = smem_u32(YS) + r * 128 + ((c16 ^ (r & 7)) << 4);
                LDMATRIX_X4(A[mt][kt], addr);
            }
        }

        float dxacc[2][2][4];
#pragma unroll
        for (int i = 0; i < 16; i++) ((float*)dxacc)[i] = 0.f;

#pragma unroll
        for (int nc = 0; nc < 4; nc++) {
            float hc[2][4][4];
#pragma unroll
            for (int i = 0; i < 32; i++) ((float*)hc)[i] = 0.f;

#pragma unroll
            for (int kt = 0; kt < 4; kt++) {
#pragma unroll
                for (int n8 = 0; n8 < 4; n8++) {
                    uint2 bb = W0F[(kt * 16 + nc * 4 + n8) * 32 + lane];
                    mma_bf16(hc[0][n8], A[0][kt], bb);
                    mma_bf16(hc[1][n8], A[1][kt], bb);
                }
            }

            uint32_t a2[2][2][4];
#pragma unroll
            for (int n8 = 0; n8 < 4; n8++) {
                float2 bb = *(const float2*)(B0S + nc * 32 + n8 * 8 + 2 * tg);
                int kt2 = n8 >> 1, half = n8 & 1;
#pragma unroll
                for (int mt = 0; mt < 2; mt++) {
                    float f0 = fmaxf(hc[mt][n8][0] + bb.x, 0.f);
                    float f1 = fmaxf(hc[mt][n8][1] + bb.y, 0.f);
                    float f2 = fmaxf(hc[mt][n8][2] + bb.x, 0.f);
                    float f3 = fmaxf(hc[mt][n8][3] + bb.y, 0.f);
                    a2[mt][kt2][half * 2 + 0] = pack_bf16x2(f0, f1);
                    a2[mt][kt2][half * 2 + 1] = pack_bf16x2(f2, f3);
                }
            }

#pragma unroll
            for (int kt2 = 0; kt2 < 2; kt2++) {
#pragma unroll
                for (int n8o = 0; n8o < 2; n8o++) {
                    uint2 b2 = W1F[((nc * 2 + kt2) * 2 + n8o) * 32 + lane];
                    mma_bf16(dxacc[0][n8o], a2[0][kt2], b2);
                    mma_bf16(dxacc[1][n8o], a2[1][kt2], b2);
                }
            }
        }

        // ---------------- epilogue: x2 = x + dx*mask (x from XS smem) --------
#pragma unroll
        for (int mt = 0; mt < 2; mt++) {
#pragma unroll
            for (int vv = 0; vv < 2; vv++) {
                int lv = w * 32 + mt * 16 + g + vv * 8;
                int y_l = lv >> 5, x_l = lv & 31;
                size_t gvox = (((size_t)b * SS + z) * SS + ty0 + y_l) * SS + tx0 + x_l;
                float m = (stoch[gvox] > 0.5f) ? 1.f : 0.f;
                const int xsi = s1 * XS_PLANE + (y_l + 1) * XROW + (x_l + 1);
#pragma unroll
                for (int n8o = 0; n8o < 2; n8o++) {
                    int c = n8o * 8 + 2 * tg;
                    float2 xv;
                    xv.x = XS[(c + 0) * XS_CH + xsi];
                    xv.y = XS[(c + 1) * XS_CH + xsi];
                    xv.x += dxacc[mt][n8o][vv * 2 + 0] * m;
                    xv.y += dxacc[mt][n8o][vv * 2 + 1] * m;
                    *(float2*)(g_x2 + gvox * 16 + c) = xv;
                    if (n8o == 0 && tg == 1) g_alpha[gvox] = xv.y;
                }
            }
        }
        __syncthreads();
    }
}

// ================= kernel C: alive(x2) maxpool + mask + writeout =============
__global__ __launch_bounds__(256)
void nca_stepB(float* __restrict__ out) {
    const int v = blockIdx.x * 256 + threadIdx.x;
    const int b = v >> 18;
    const int r = v & 262143;
    const int d = r >> 12;
    const int h = (r >> 6) & 63;
    const int w = r & 63;

    float maxa = -1e30f;
#pragma unroll
    for (int dz = -1; dz <= 1; dz++) {
        int dd = d + dz;
        if (dd < 0 || dd >= SS) continue;
#pragma unroll
        for (int dy = -1; dy <= 1; dy++) {
            int hh = h + dy;
            if (hh < 0 || hh >= SS) continue;
#pragma unroll
            for (int dxx = -1; dxx <= 1; dxx++) {
                int ww = w + dxx;
                if (ww < 0 || ww >= SS) continue;
                maxa = fmaxf(maxa, g_alpha[(((b * SS + dd) * SS + hh) * SS + ww)]);
            }
        }
    }
    const bool life = (g_pre[v] != 0) && (maxa > 0.1f);
    const float s = life ? 1.f : 0.f;

    const float4* xi = (const float4*)g_x2 + (size_t)v * 4;
    float4* o = (float4*)out + (size_t)v * 4;
#pragma unroll
    for (int q = 0; q < 4; q++) {
        float4 t = xi[q];
        t.x *= s; t.y *= s; t.z *= s; t.w *= s;
        o[q] = t;
    }
}

extern "C" void kernel_launch(void* const* d_in, const int* in_sizes, int n_in,
                              void* d_out, int out_size) {
    const float* x     = (const float*)d_in[0];
    const float* w0    = (const float*)d_in[1];
    const float* b0    = (const float*)d_in[2];
    const float* w1    = (const float*)d_in[3];
    const float* stoch = (const float*)d_in[4];

    nca_prep<<<1, 256>>>(w0, w1);

    cudaFuncSetAttribute(nca_fused, cudaFuncAttributeMaxDynamicSharedMemorySize, F_SMEM_BYTES);
    dim3 gridF(SS / TX, SS / TY, SB * (SS / TZ));   // (2, 4, 64)
    nca_fused<<<gridF, 512, F_SMEM_BYTES>>>(x, b0, stoch);

    nca_stepB<<<NVOX / 256, 256>>>((float*)d_out);
}

// round 6
// speedup vs baseline: 4.6632x; 1.0767x over previous
#include <cuda_runtime.h>
#include <cuda_bf16.h>
#include <cstdint>

// NCA 3D update step — fused conv+GEMM (bf16 HMMA) writing x2 directly to out;
// second kernel only zeroes dead voxels.
//   x:[4,64,64,64,16] f32, w0:[128,64], b0:[128], w1:[16,128], stoch:[4,64^3,1]
// out = (x + dx*(stoch>0.5)) * (pre_life & alive(x2))
// y is K-PERMUTED in YS smem: y'[4c+s] = {x_c, gx_c, gy_c, gz_c}; 1/32 folded into W0.

#define SB 4
#define SS 64
#define SC 16
#define NVOX (SB * SS * SS * SS)

// ---------------- device scratch ----------------
__device__ float         g_alpha[NVOX];              // 4 MB
__device__ unsigned char g_pre[NVOX];                // 1 MB

__device__ __forceinline__ uint32_t smem_u32(const void* p) {
    uint32_t a;
    asm("{ .reg .u64 t; cvta.to.shared.u64 t, %1; cvt.u32.u64 %0, t; }" : "=r"(a) : "l"(p));
    return a;
}
__device__ __forceinline__ uint32_t pack_bf16x2(float lo, float hi) {
    uint32_t r;
    asm("cvt.rn.bf16x2.f32 %0, %1, %2;" : "=r"(r) : "f"(hi), "f"(lo));
    return r;
}
__device__ __forceinline__ void mma_bf16(float* c, const uint32_t* a, const uint2 b) {
    asm volatile(
        "mma.sync.aligned.m16n8k16.row.col.f32.bf16.bf16.f32 "
        "{%0,%1,%2,%3}, {%4,%5,%6,%7}, {%8,%9}, {%0,%1,%2,%3};"
        : "+f"(c[0]), "+f"(c[1]), "+f"(c[2]), "+f"(c[3])
        : "r"(a[0]), "r"(a[1]), "r"(a[2]), "r"(a[3]), "r"(b.x), "r"(b.y));
}
#define LDMATRIX_X4(r, addr)                                                   \
    asm volatile("ldmatrix.sync.aligned.m8n8.x4.shared.b16 {%0,%1,%2,%3}, [%4];" \
        : "=r"((r)[0]), "=r"((r)[1]), "=r"((r)[2]), "=r"((r)[3]) : "r"(addr))

// ================= fused kernel: conv -> YS(smem) -> double GEMM -> out ======
// CTA: 512 threads, 16x32 (h,w) tile, 4 z-slices, rolling 3-plane window.
#define TY 16
#define TX 32
#define TZ 4
#define XROW 35                   // 34 used + 1 pad
#define XS_PLANE (18 * XROW)      // 630
#define XS_CH    (3 * XS_PLANE)   // 1890
#define XS_BYTES (16 * XS_CH * 4) // 120960
#define YS_BYTES (512 * 128)      // 65536
#define F_SMEM_BYTES (XS_BYTES + YS_BYTES + 16384 + 4096 + 512)

__device__ __forceinline__ void load_plane(float* XS, const float* __restrict__ x,
                                           int b, int zp, int ty0, int tx0,
                                           int slot, int tid) {
    const bool zin = (zp >= 0 && zp < SS);
    for (int i = tid; i < 18 * 34; i += 512) {
        int hy = i / 34;
        int wx = i % 34;
        int dst = slot * XS_PLANE + hy * XROW + wx;
        int gy2 = hy - 1 + ty0, gx2 = wx - 1 + tx0;
        if (zin && gy2 >= 0 && gy2 < SS && gx2 >= 0 && gx2 < SS) {
            const float4* p = (const float4*)(x + ((((size_t)b * SS + zp) * SS + gy2) * SS + gx2) * SC);
#pragma unroll
            for (int q = 0; q < 4; q++) {
                float4 v = p[q];
                XS[(4 * q + 0) * XS_CH + dst] = v.x;
                XS[(4 * q + 1) * XS_CH + dst] = v.y;
                XS[(4 * q + 2) * XS_CH + dst] = v.z;
                XS[(4 * q + 3) * XS_CH + dst] = v.w;
            }
        } else {
#pragma unroll
            for (int c = 0; c < 16; c++) XS[c * XS_CH + dst] = 0.f;
        }
    }
}

__global__ __launch_bounds__(512, 1)
void nca_fused(const float* __restrict__ x, const float* __restrict__ w0g,
               const float* __restrict__ w1g, const float* __restrict__ b0,
               const float* __restrict__ stoch, float* __restrict__ out) {
    extern __shared__ float SM[];
    float*   XS  = SM;
    uint8_t* YS  = (uint8_t*)(SM + 16 * XS_CH);
    uint2*   W0F = (uint2*)(YS + YS_BYTES);
    uint2*   W1F = W0F + 64 * 32;
    float*   B0S = (float*)(W1F + 16 * 32);

    const int tid = threadIdx.x;

    // build mma b-fragments in smem directly from w0/w1 (K-permuted, scaled)
    {
        const int lane = tid & 31, g = lane >> 2, tg = lane & 3;
        for (int t = tid; t < 64 * 32; t += 512) {
            int f = t >> 5;
            int kt = f >> 4, nt = f & 15;
            int n = nt * 8 + ((t & 31) >> 2);
            int tgq = (t & 31) & 3;
            int kb = kt * 16 + 2 * tgq;
            float e[4];
#pragma unroll
            for (int q = 0; q < 4; q++) {
                int kp = kb + (q >> 1) * 8 + (q & 1);
                int ko = (kp & 3) * 16 + (kp >> 2);
                float s = (ko >= 16) ? (1.f / 32.f) : 1.f;
                e[q] = w0g[n * 64 + ko] * s;
            }
            uint2 v;
            v.x = pack_bf16x2(e[0], e[1]);
            v.y = pack_bf16x2(e[2], e[3]);
            W0F[t] = v;
        }
        for (int t = tid; t < 16 * 32; t += 512) {
            int f = t >> 5;
            int kt = f >> 1, nt = f & 1;
            int n = nt * 8 + ((t & 31) >> 2);
            int tgq = (t & 31) & 3;
            int kb = kt * 16 + 2 * tgq;
            uint2 v;
            v.x = pack_bf16x2(w1g[n * 128 + kb],     w1g[n * 128 + kb + 1]);
            v.y = pack_bf16x2(w1g[n * 128 + kb + 8], w1g[n * 128 + kb + 9]);
            W1F[t] = v;
        }
        if (tid < 128) B0S[tid] = b0[tid];
        (void)g; (void)tg;
    }

    const int b   = blockIdx.z >> 4;
    const int z0  = (blockIdx.z & 15) * TZ;
    const int ty0 = blockIdx.y * TY;
    const int tx0 = blockIdx.x * TX;

    load_plane(XS, x, b, z0 - 1, ty0, tx0, ((z0 - 1) + 3) % 3, tid);
    load_plane(XS, x, b, z0,     ty0, tx0, z0 % 3,             tid);

    // conv mapping: cg(4 channels) x ly(16) x tx4(8 groups of 4 x-voxels)
    const int cg  = tid >> 7;
    const int sub = tid & 127;
    const int ly  = sub >> 3;
    const int tx4 = sub & 7;
    const int gh  = ty0 + ly;
    const int gx0 = tx0 + 4 * tx4;

    // gemm mapping
    const int w    = tid >> 5;
    const int lane = tid & 31;
    const int g    = lane >> 2;
    const int tg   = lane & 3;

    for (int z = z0; z < z0 + TZ; z++) {
        load_plane(XS, x, b, z + 1, ty0, tx0, (z + 1) % 3, tid);
        __syncthreads();

        const int s0 = ((z - 1) + 3) % 3, s1 = z % 3, s2 = (z + 1) % 3;
        const size_t voxbase = (((size_t)b * SS + z) * SS + gh) * SS + gx0;
        const int lrow0 = ly * TX + 4 * tx4;

        // ---------------- conv phase: y' -> YS ----------------
#pragma unroll
        for (int cpair = 0; cpair < 2; cpair++) {
            float st[2][4][4];
#pragma unroll
            for (int ci = 0; ci < 2; ci++) {
                const int c = cg * 4 + cpair * 2 + ci;
                const float* base = XS + c * XS_CH;

                float a[3][6], d[3][6], ctrv[4], cm[6];
#pragma unroll
                for (int dy = 0; dy < 3; dy++) {
#pragma unroll
                    for (int j = 0; j < 6; j++) {
                        int idx = (ly + dy) * XROW + 4 * tx4 + j;
                        float vm = base[s0 * XS_PLANE + idx];
                        float vc = base[s1 * XS_PLANE + idx];
                        float vp = base[s2 * XS_PLANE + idx];
                        a[dy][j] = fmaf(2.f, vc, vm) + vp;
                        d[dy][j] = vp - vm;
                        if (c == 3) {
                            float m = fmaxf(fmaxf(vm, vc), vp);
                            cm[j] = (dy == 0) ? m : fmaxf(cm[j], m);
                        }
                        if (dy == 1 && j >= 1 && j <= 4) ctrv[j - 1] = vc;
                    }
                }
#pragma unroll
                for (int v = 0; v < 4; v++) {
                    float gx = (a[0][v + 2] - a[0][v])
                             + 2.f * (a[1][v + 2] - a[1][v])
                             + (a[2][v + 2] - a[2][v]);
                    float sx0 = fmaf(2.f, a[0][v + 1], a[0][v]) + a[0][v + 2];
                    float sx2 = fmaf(2.f, a[2][v + 1], a[2][v]) + a[2][v + 2];
                    float gy = sx2 - sx0;
                    float t0 = fmaf(2.f, d[0][v + 1], d[0][v]) + d[0][v + 2];
                    float t1 = fmaf(2.f, d[1][v + 1], d[1][v]) + d[1][v + 2];
                    float t2 = fmaf(2.f, d[2][v + 1], d[2][v]) + d[2][v + 2];
                    float gz = fmaf(2.f, t1, t0) + t2;
                    st[ci][v][0] = ctrv[v];
                    st[ci][v][1] = gx;
                    st[ci][v][2] = gy;
                    st[ci][v][3] = gz;
                }
                if (c == 3) {
                    uchar4 pre;
                    pre.x = (fmaxf(fmaxf(cm[0], cm[1]), cm[2]) > 0.1f) ? 1 : 0;
                    pre.y = (fmaxf(fmaxf(cm[1], cm[2]), cm[3]) > 0.1f) ? 1 : 0;
                    pre.z = (fmaxf(fmaxf(cm[2], cm[3]), cm[4]) > 0.1f) ? 1 : 0;
                    pre.w = (fmaxf(fmaxf(cm[3], cm[4]), cm[5]) > 0.1f) ? 1 : 0;
                    *(uchar4*)(g_pre + voxbase) = pre;
                }
            }
            const int c16 = cg * 2 + cpair;
#pragma unroll
            for (int v = 0; v < 4; v++) {
                int row = lrow0 + v;
                uint4 o;
                o.x = pack_bf16x2(st[0][v][0], st[0][v][1]);
                o.y = pack_bf16x2(st[0][v][2], st[0][v][3]);
                o.z = pack_bf16x2(st[1][v][0], st[1][v][1]);
                o.w = pack_bf16x2(st[1][v][2], st[1][v][3]);
                *(uint4*)(YS + row * 128 + ((c16 ^ (row & 7)) << 4)) = o;
            }
        }
        __syncthreads();

        // ---------------- GEMM phase ----------------
        uint32_t A[2][4][4];
#pragma unroll
        for (int mt = 0; mt < 2; mt++) {
#pragma unroll
            for (int kt = 0; kt < 4; kt++) {
                int r   = w * 32 + mt * 16 + (lane & 15);
                int c16 = kt * 2 + (lane >> 4);
                uint32_t addr = smem_u32(YS) + r * 128 + ((c16 ^ (r & 7)) << 4);
                LDMATRIX_X4(A[mt][kt], addr);
            }
        }

        float dxacc[2][2][4];
#pragma unroll
        for (int i = 0; i < 16; i++) ((float*)dxacc)[i] = 0.f;

#pragma unroll
        for (int nc = 0; nc < 4; nc++) {
            float hc[2][4][4];
#pragma unroll
            for (int i = 0; i < 32; i++) ((float*)hc)[i] = 0.f;

#pragma unroll
            for (int kt = 0; kt < 4; kt++) {
#pragma unroll
                for (int n8 = 0; n8 < 4; n8++) {
                    uint2 bb = W0F[(kt * 16 + nc * 4 + n8) * 32 + lane];
                    mma_bf16(hc[0][n8], A[0][kt], bb);
                    mma_bf16(hc[1][n8], A[1][kt], bb);
                }
            }

            uint32_t a2[2][2][4];
#pragma unroll
            for (int n8 = 0; n8 < 4; n8++) {
                float2 bb = *(const float2*)(B0S + nc * 32 + n8 * 8 + 2 * tg);
                int kt2 = n8 >> 1, half = n8 & 1;
#pragma unroll
                for (int mt = 0; mt < 2; mt++) {
                    float f0 = fmaxf(hc[mt][n8][0] + bb.x, 0.f);
                    float f1 = fmaxf(hc[mt][n8][1] + bb.y, 0.f);
                    float f2 = fmaxf(hc[mt][n8][2] + bb.x, 0.f);
                    float f3 = fmaxf(hc[mt][n8][3] + bb.y, 0.f);
                    a2[mt][kt2][half * 2 + 0] = pack_bf16x2(f0, f1);
                    a2[mt][kt2][half * 2 + 1] = pack_bf16x2(f2, f3);
                }
            }

#pragma unroll
            for (int kt2 = 0; kt2 < 2; kt2++) {
#pragma unroll
                for (int n8o = 0; n8o < 2; n8o++) {
                    uint2 b2 = W1F[((nc * 2 + kt2) * 2 + n8o) * 32 + lane];
                    mma_bf16(dxacc[0][n8o], a2[0][kt2], b2);
                    mma_bf16(dxacc[1][n8o], a2[1][kt2], b2);
                }
            }
        }

        // ------------- epilogue: out = x + dx*mask (x from XS smem) ----------
#pragma unroll
        for (int mt = 0; mt < 2; mt++) {
#pragma unroll
            for (int vv = 0; vv < 2; vv++) {
                int lv = w * 32 + mt * 16 + g + vv * 8;
                int y_l = lv >> 5, x_l = lv & 31;
                size_t gvox = (((size_t)b * SS + z) * SS + ty0 + y_l) * SS + tx0 + x_l;
                float m = (stoch[gvox] > 0.5f) ? 1.f : 0.f;
                const int xsi = s1 * XS_PLANE + (y_l + 1) * XROW + (x_l + 1);
#pragma unroll
                for (int n8o = 0; n8o < 2; n8o++) {
                    int c = n8o * 8 + 2 * tg;
                    float2 xv;
                    xv.x = XS[(c + 0) * XS_CH + xsi];
                    xv.y = XS[(c + 1) * XS_CH + xsi];
                    xv.x += dxacc[mt][n8o][vv * 2 + 0] * m;
                    xv.y += dxacc[mt][n8o][vv * 2 + 1] * m;
                    *(float2*)(out + gvox * 16 + c) = xv;
                    if (n8o == 0 && tg == 1) g_alpha[gvox] = xv.y;
                }
            }
        }
        __syncthreads();
    }
}

// ================= kill pass: zero voxels where life == 0 ====================
__global__ __launch_bounds__(256)
void nca_kill(float* __restrict__ out) {
    const int v = blockIdx.x * 256 + threadIdx.x;
    const int b = v >> 18;
    const int r = v & 262143;
    const int d = r >> 12;
    const int h = (r >> 6) & 63;
    const int w = r & 63;

    bool life = (g_pre[v] != 0);
    if (life) {
        float maxa = -1e30f;
#pragma unroll
        for (int dz = -1; dz <= 1; dz++) {
            int dd = d + dz;
            if (dd < 0 || dd >= SS) continue;
#pragma unroll
            for (int dy = -1; dy <= 1; dy++) {
                int hh = h + dy;
                if (hh < 0 || hh >= SS) continue;
#pragma unroll
                for (int dxx = -1; dxx <= 1; dxx++) {
                    int ww = w + dxx;
                    if (ww < 0 || ww >= SS) continue;
                    maxa = fmaxf(maxa, g_alpha[(((b * SS + dd) * SS + hh) * SS + ww)]);
                }
            }
        }
        life = (maxa > 0.1f);
    }
    if (!life) {
        float4 zz = make_float4(0.f, 0.f, 0.f, 0.f);
        float4* o = (float4*)out + (size_t)v * 4;
#pragma unroll
        for (int q = 0; q < 4; q++) o[q] = zz;
    }
}

extern "C" void kernel_launch(void* const* d_in, const int* in_sizes, int n_in,
                              void* d_out, int out_size) {
    const float* x     = (const float*)d_in[0];
    const float* w0    = (const float*)d_in[1];
    const float* b0    = (const float*)d_in[2];
    const float* w1    = (const float*)d_in[3];
    const float* stoch = (const float*)d_in[4];

    cudaFuncSetAttribute(nca_fused, cudaFuncAttributeMaxDynamicSharedMemorySize, F_SMEM_BYTES);
    dim3 gridF(SS / TX, SS / TY, SB * (SS / TZ));   // (2, 4, 64)
    nca_fused<<<gridF, 512, F_SMEM_BYTES>>>(x, w0, w1, b0, stoch, (float*)d_out);

    nca_kill<<<NVOX / 256, 256>>>((float*)d_out);
}

// round 7
// speedup vs baseline: 4.6882x; 1.0053x over previous
#include <cuda_runtime.h>
#include <cuda_bf16.h>
#include <cstdint>

// NCA 3D update step — fused conv+GEMM (bf16 HMMA) writing x2 directly to out;
// kill pass (split into 4 z-slab launches) zeroes dead voxels.
//   x:[4,64,64,64,16] f32, w0:[128,64], b0:[128], w1:[16,128], stoch:[4,64^3,1]
// out = (x + dx*(stoch>0.5)) * (pre_life & alive(x2))
// y is K-PERMUTED in YS smem: y'[4c+s] = {x_c, gx_c, gy_c, gz_c}; 1/32 folded into W0.

#define SB 4
#define SS 64
#define SC 16
#define NVOX (SB * SS * SS * SS)

// ---------------- device scratch ----------------
__device__ float         g_alpha[NVOX];              // 4 MB
__device__ unsigned char g_pre[NVOX];                // 1 MB

__device__ __forceinline__ uint32_t smem_u32(const void* p) {
    uint32_t a;
    asm("{ .reg .u64 t; cvta.to.shared.u64 t, %1; cvt.u32.u64 %0, t; }" : "=r"(a) : "l"(p));
    return a;
}
__device__ __forceinline__ uint32_t pack_bf16x2(float lo, float hi) {
    uint32_t r;
    asm("cvt.rn.bf16x2.f32 %0, %1, %2;" : "=r"(r) : "f"(hi), "f"(lo));
    return r;
}
__device__ __forceinline__ void mma_bf16(float* c, const uint32_t* a, const uint2 b) {
    asm volatile(
        "mma.sync.aligned.m16n8k16.row.col.f32.bf16.bf16.f32 "
        "{%0,%1,%2,%3}, {%4,%5,%6,%7}, {%8,%9}, {%0,%1,%2,%3};"
        : "+f"(c[0]), "+f"(c[1]), "+f"(c[2]), "+f"(c[3])
        : "r"(a[0]), "r"(a[1]), "r"(a[2]), "r"(a[3]), "r"(b.x), "r"(b.y));
}
#define LDMATRIX_X4(r, addr)                                                   \
    asm volatile("ldmatrix.sync.aligned.m8n8.x4.shared.b16 {%0,%1,%2,%3}, [%4];" \
        : "=r"((r)[0]), "=r"((r)[1]), "=r"((r)[2]), "=r"((r)[3]) : "r"(addr))

// ================= fused kernel: conv -> YS(smem) -> double GEMM -> out ======
// CTA: 512 threads, 16x32 (h,w) tile, 8 z-slices, rolling 3-plane window.
#define TY 16
#define TX 32
#define TZ 8
#define XROW 35                   // 34 used + 1 pad
#define XS_PLANE (18 * XROW)      // 630
#define XS_CH    (3 * XS_PLANE)   // 1890
#define XS_BYTES (16 * XS_CH * 4) // 120960
#define YS_BYTES (512 * 128)      // 65536
#define F_SMEM_BYTES (XS_BYTES + YS_BYTES + 16384 + 4096 + 512)

__device__ __forceinline__ void load_plane(float* XS, const float* __restrict__ x,
                                           int b, int zp, int ty0, int tx0,
                                           int slot, int tid) {
    const bool zin = (zp >= 0 && zp < SS);
    for (int i = tid; i < 18 * 34; i += 512) {
        int hy = i / 34;
        int wx = i % 34;
        int dst = slot * XS_PLANE + hy * XROW + wx;
        int gy2 = hy - 1 + ty0, gx2 = wx - 1 + tx0;
        if (zin && gy2 >= 0 && gy2 < SS && gx2 >= 0 && gx2 < SS) {
            const float4* p = (const float4*)(x + ((((size_t)b * SS + zp) * SS + gy2) * SS + gx2) * SC);
#pragma unroll
            for (int q = 0; q < 4; q++) {
                float4 v = p[q];
                XS[(4 * q + 0) * XS_CH + dst] = v.x;
                XS[(4 * q + 1) * XS_CH + dst] = v.y;
                XS[(4 * q + 2) * XS_CH + dst] = v.z;
                XS[(4 * q + 3) * XS_CH + dst] = v.w;
            }
        } else {
#pragma unroll
            for (int c = 0; c < 16; c++) XS[c * XS_CH + dst] = 0.f;
        }
    }
}

__global__ __launch_bounds__(512, 1)
void nca_fused(const float* __restrict__ x, const float* __restrict__ w0g,
               const float* __restrict__ w1g, const float* __restrict__ b0,
               const float* __restrict__ stoch, float* __restrict__ out) {
    extern __shared__ float SM[];
    float*   XS  = SM;
    uint8_t* YS  = (uint8_t*)(SM + 16 * XS_CH);
    uint2*   W0F = (uint2*)(YS + YS_BYTES);
    uint2*   W1F = W0F + 64 * 32;
    float*   B0S = (float*)(W1F + 16 * 32);

    const int tid = threadIdx.x;

    // build mma b-fragments in smem directly from w0/w1 (K-permuted, scaled)
    {
        for (int t = tid; t < 64 * 32; t += 512) {
            int f = t >> 5;
            int kt = f >> 4, nt = f & 15;
            int n = nt * 8 + ((t & 31) >> 2);
            int tgq = (t & 31) & 3;
            int kb = kt * 16 + 2 * tgq;
            float e[4];
#pragma unroll
            for (int q = 0; q < 4; q++) {
                int kp = kb + (q >> 1) * 8 + (q & 1);
                int ko = (kp & 3) * 16 + (kp >> 2);
                float s = (ko >= 16) ? (1.f / 32.f) : 1.f;
                e[q] = w0g[n * 64 + ko] * s;
            }
            uint2 v;
            v.x = pack_bf16x2(e[0], e[1]);
            v.y = pack_bf16x2(e[2], e[3]);
            W0F[t] = v;
        }
        for (int t = tid; t < 16 * 32; t += 512) {
            int f = t >> 5;
            int kt = f >> 1, nt = f & 1;
            int n = nt * 8 + ((t & 31) >> 2);
            int tgq = (t & 31) & 3;
            int kb = kt * 16 + 2 * tgq;
            uint2 v;
            v.x = pack_bf16x2(w1g[n * 128 + kb],     w1g[n * 128 + kb + 1]);
            v.y = pack_bf16x2(w1g[n * 128 + kb + 8], w1g[n * 128 + kb + 9]);
            W1F[t] = v;
        }
        if (tid < 128) B0S[tid] = b0[tid];
    }

    const int b   = blockIdx.z >> 3;
    const int z0  = (blockIdx.z & 7) * TZ;
    const int ty0 = blockIdx.y * TY;
    const int tx0 = blockIdx.x * TX;

    load_plane(XS, x, b, z0 - 1, ty0, tx0, ((z0 - 1) + 3) % 3, tid);
    load_plane(XS, x, b, z0,     ty0, tx0, z0 % 3,             tid);

    // conv mapping: cg(4 channels) x ly(16) x tx4(8 groups of 4 x-voxels)
    const int cg  = tid >> 7;
    const int sub = tid & 127;
    const int ly  = sub >> 3;
    const int tx4 = sub & 7;
    const int gh  = ty0 + ly;
    const int gx0 = tx0 + 4 * tx4;

    // gemm mapping
    const int w    = tid >> 5;
    const int lane = tid & 31;
    const int g    = lane >> 2;
    const int tg   = lane & 3;

    for (int z = z0; z < z0 + TZ; z++) {
        load_plane(XS, x, b, z + 1, ty0, tx0, (z + 1) % 3, tid);
        __syncthreads();

        const int s0 = ((z - 1) + 3) % 3, s1 = z % 3, s2 = (z + 1) % 3;
        const size_t voxbase = (((size_t)b * SS + z) * SS + gh) * SS + gx0;
        const int lrow0 = ly * TX + 4 * tx4;

        // ---------------- conv phase: y' -> YS ----------------
#pragma unroll
        for (int cpair = 0; cpair < 2; cpair++) {
            float st[2][4][4];
#pragma unroll
            for (int ci = 0; ci < 2; ci++) {
                const int c = cg * 4 + cpair * 2 + ci;
                const float* base = XS + c * XS_CH;

                float a[3][6], d[3][6], ctrv[4], cm[6];
#pragma unroll
                for (int dy = 0; dy < 3; dy++) {
#pragma unroll
                    for (int j = 0; j < 6; j++) {
                        int idx = (ly + dy) * XROW + 4 * tx4 + j;
                        float vm = base[s0 * XS_PLANE + idx];
                        float vc = base[s1 * XS_PLANE + idx];
                        float vp = base[s2 * XS_PLANE + idx];
                        a[dy][j] = fmaf(2.f, vc, vm) + vp;
                        d[dy][j] = vp - vm;
                        if (c == 3) {
                            float m = fmaxf(fmaxf(vm, vc), vp);
                            cm[j] = (dy == 0) ? m : fmaxf(cm[j], m);
                        }
                        if (dy == 1 && j >= 1 && j <= 4) ctrv[j - 1] = vc;
                    }
                }
#pragma unroll
                for (int v = 0; v < 4; v++) {
                    float gx = (a[0][v + 2] - a[0][v])
                             + 2.f * (a[1][v + 2] - a[1][v])
                             + (a[2][v + 2] - a[2][v]);
                    float sx0 = fmaf(2.f, a[0][v + 1], a[0][v]) + a[0][v + 2];
                    float sx2 = fmaf(2.f, a[2][v + 1], a[2][v]) + a[2][v + 2];
                    float gy = sx2 - sx0;
                    float t0 = fmaf(2.f, d[0][v + 1], d[0][v]) + d[0][v + 2];
                    float t1 = fmaf(2.f, d[1][v + 1], d[1][v]) + d[1][v + 2];
                    float t2 = fmaf(2.f, d[2][v + 1], d[2][v]) + d[2][v + 2];
                    float gz = fmaf(2.f, t1, t0) + t2;
                    st[ci][v][0] = ctrv[v];
                    st[ci][v][1] = gx;
                    st[ci][v][2] = gy;
                    st[ci][v][3] = gz;
                }
                if (c == 3) {
                    uchar4 pre;
                    pre.x = (fmaxf(fmaxf(cm[0], cm[1]), cm[2]) > 0.1f) ? 1 : 0;
                    pre.y = (fmaxf(fmaxf(cm[1], cm[2]), cm[3]) > 0.1f) ? 1 : 0;
                    pre.z = (fmaxf(fmaxf(cm[2], cm[3]), cm[4]) > 0.1f) ? 1 : 0;
                    pre.w = (fmaxf(fmaxf(cm[3], cm[4]), cm[5]) > 0.1f) ? 1 : 0;
                    *(uchar4*)(g_pre + voxbase) = pre;
                }
            }
            const int c16 = cg * 2 + cpair;
#pragma unroll
            for (int v = 0; v < 4; v++) {
                int row = lrow0 + v;
                uint4 o;
                o.x = pack_bf16x2(st[0][v][0], st[0][v][1]);
                o.y = pack_bf16x2(st[0][v][2], st[0][v][3]);
                o.z = pack_bf16x2(st[1][v][0], st[1][v][1]);
                o.w = pack_bf16x2(st[1][v][2], st[1][v][3]);
                *(uint4*)(YS + row * 128 + ((c16 ^ (row & 7)) << 4)) = o;
            }
        }
        __syncthreads();

        // ---------------- GEMM phase ----------------
        uint32_t A[2][4][4];
#pragma unroll
        for (int mt = 0; mt < 2; mt++) {
#pragma unroll
            for (int kt = 0; kt < 4; kt++) {
                int r   = w * 32 + mt * 16 + (lane & 15);
                int c16 = kt * 2 + (lane >> 4);
                uint32_t addr = smem_u32(YS) + r * 128 + ((c16 ^ (r & 7)) << 4);
                LDMATRIX_X4(A[mt][kt], addr);
            }
        }

        float dxacc[2][2][4];
#pragma unroll
        for (int i = 0; i < 16; i++) ((float*)dxacc)[i] = 0.f;

#pragma unroll
        for (int nc = 0; nc < 4; nc++) {
            float hc[2][4][4];
#pragma unroll
            for (int i = 0; i < 32; i++) ((float*)hc)[i] = 0.f;

#pragma unroll
            for (int kt = 0; kt < 4; kt++) {
#pragma unroll
                for (int n8 = 0; n8 < 4; n8++) {
                    uint2 bb = W0F[(kt * 16 + nc * 4 + n8) * 32 + lane];
                    mma_bf16(hc[0][n8], A[0][kt], bb);
                    mma_bf16(hc[1][n8], A[1][kt], bb);
                }
            }

            uint32_t a2[2][2][4];
#pragma unroll
            for (int n8 = 0; n8 < 4; n8++) {
                float2 bb = *(const float2*)(B0S + nc * 32 + n8 * 8 + 2 * tg);
                int kt2 = n8 >> 1, half = n8 & 1;
#pragma unroll
                for (int mt = 0; mt < 2; mt++) {
                    float f0 = fmaxf(hc[mt][n8][0] + bb.x, 0.f);
                    float f1 = fmaxf(hc[mt][n8][1] + bb.y, 0.f);
                    float f2 = fmaxf(hc[mt][n8][2] + bb.x, 0.f);
                    float f3 = fmaxf(hc[mt][n8][3] + bb.y, 0.f);
                    a2[mt][kt2][half * 2 + 0] = pack_bf16x2(f0, f1);
                    a2[mt][kt2][half * 2 + 1] = pack_bf16x2(f2, f3);
                }
            }

#pragma unroll
            for (int kt2 = 0; kt2 < 2; kt2++) {
#pragma unroll
                for (int n8o = 0; n8o < 2; n8o++) {
                    uint2 b2 = W1F[((nc * 2 + kt2) * 2 + n8o) * 32 + lane];
                    mma_bf16(dxacc[0][n8o], a2[0][kt2], b2);
                    mma_bf16(dxacc[1][n8o], a2[1][kt2], b2);
                }
            }
        }

        // ------------- epilogue: out = x + dx*mask (x from XS smem) ----------
#pragma unroll
        for (int mt = 0; mt < 2; mt++) {
#pragma unroll
            for (int vv = 0; vv < 2; vv++) {
                int lv = w * 32 + mt * 16 + g + vv * 8;
                int y_l = lv >> 5, x_l = lv & 31;
                size_t gvox = (((size_t)b * SS + z) * SS + ty0 + y_l) * SS + tx0 + x_l;
                float m = (stoch[gvox] > 0.5f) ? 1.f : 0.f;
                const int xsi = s1 * XS_PLANE + (y_l + 1) * XROW + (x_l + 1);
#pragma unroll
                for (int n8o = 0; n8o < 2; n8o++) {
                    int c = n8o * 8 + 2 * tg;
                    float2 xv;
                    xv.x = XS[(c + 0) * XS_CH + xsi];
                    xv.y = XS[(c + 1) * XS_CH + xsi];
                    xv.x += dxacc[mt][n8o][vv * 2 + 0] * m;
                    xv.y += dxacc[mt][n8o][vv * 2 + 1] * m;
                    *(float2*)(out + gvox * 16 + c) = xv;
                    if (n8o == 0 && tg == 1) g_alpha[gvox] = xv.y;
                }
            }
        }
        __syncthreads();
    }
}

// ================= kill pass: zero voxels where life == 0 ====================
// Split into 4 z-slab launches (also makes ncu -s 5 land on nca_fused).
__global__ __launch_bounds__(256)
void nca_kill(float* __restrict__ out, int vbase) {
    const int v = vbase + blockIdx.x * 256 + threadIdx.x;
    const int b = v >> 18;
    const int r = v & 262143;
    const int d = r >> 12;
    const int h = (r >> 6) & 63;
    const int w = r & 63;

    bool life = (g_pre[v] != 0);
    if (life) {
        float maxa = -1e30f;
#pragma unroll
        for (int dz = -1; dz <= 1; dz++) {
            int dd = d + dz;
            if (dd < 0 || dd >= SS) continue;
#pragma unroll
            for (int dy = -1; dy <= 1; dy++) {
                int hh = h + dy;
                if (hh < 0 || hh >= SS) continue;
#pragma unroll
                for (int dxx = -1; dxx <= 1; dxx++) {
                    int ww = w + dxx;
                    if (ww < 0 || ww >= SS) continue;
                    maxa = fmaxf(maxa, g_alpha[(((b * SS + dd) * SS + hh) * SS + ww)]);
                }
            }
        }
        life = (maxa > 0.1f);
    }
    if (!life) {
        float4 zz = make_float4(0.f, 0.f, 0.f, 0.f);
        float4* o = (float4*)out + (size_t)v * 4;
#pragma unroll
        for (int q = 0; q < 4; q++) o[q] = zz;
    }
}

extern "C" void kernel_launch(void* const* d_in, const int* in_sizes, int n_in,
                              void* d_out, int out_size) {
    const float* x     = (const float*)d_in[0];
    const float* w0    = (const float*)d_in[1];
    const float* b0    = (const float*)d_in[2];
    const float* w1    = (const float*)d_in[3];
    const float* stoch = (const float*)d_in[4];

    cudaFuncSetAttribute(nca_fused, cudaFuncAttributeMaxDynamicSharedMemorySize, F_SMEM_BYTES);
    dim3 gridF(SS / TX, SS / TY, SB * (SS / TZ));   // (2, 4, 32)
    nca_fused<<<gridF, 512, F_SMEM_BYTES>>>(x, w0, w1, b0, stoch, (float*)d_out);

    const int quarter = NVOX / 4;
    for (int q = 0; q < 4; q++)
        nca_kill<<<quarter / 256, 256>>>((float*)d_out, q * quarter);
}

// round 8
// speedup vs baseline: 4.9895x; 1.0643x over previous
#include <cuda_runtime.h>
#include <cuda_bf16.h>
#include <cstdint>

// NCA 3D update step — fused conv+GEMM (bf16 HMMA) writing x2 directly to out;
// single kill pass zeroes dead voxels (4-wide per thread).
//   x:[4,64,64,64,16] f32, w0:[128,64], b0:[128], w1:[16,128], stoch:[4,64^3,1]
// out = (x + dx*(stoch>0.5)) * (pre_life & alive(x2))
// y is K-PERMUTED in YS smem: y'[4c+s] = {x_c, gx_c, gy_c, gz_c}; 1/32 folded into W0.

#define SB 4
#define SS 64
#define SC 16
#define NVOX (SB * SS * SS * SS)

// ---------------- device scratch ----------------
__device__ float         g_alpha[NVOX];              // 4 MB
__device__ unsigned char g_pre[NVOX];                // 1 MB

__device__ __forceinline__ uint32_t smem_u32(const void* p) {
    uint32_t a;
    asm("{ .reg .u64 t; cvta.to.shared.u64 t, %1; cvt.u32.u64 %0, t; }" : "=r"(a) : "l"(p));
    return a;
}
__device__ __forceinline__ uint32_t pack_bf16x2(float lo, float hi) {
    uint32_t r;
    asm("cvt.rn.bf16x2.f32 %0, %1, %2;" : "=r"(r) : "f"(hi), "f"(lo));
    return r;
}
__device__ __forceinline__ void mma_bf16(float* c, const uint32_t* a, const uint2 b) {
    asm volatile(
        "mma.sync.aligned.m16n8k16.row.col.f32.bf16.bf16.f32 "
        "{%0,%1,%2,%3}, {%4,%5,%6,%7}, {%8,%9}, {%0,%1,%2,%3};"
        : "+f"(c[0]), "+f"(c[1]), "+f"(c[2]), "+f"(c[3])
        : "r"(a[0]), "r"(a[1]), "r"(a[2]), "r"(a[3]), "r"(b.x), "r"(b.y));
}
#define LDMATRIX_X4(r, addr)                                                   \
    asm volatile("ldmatrix.sync.aligned.m8n8.x4.shared.b16 {%0,%1,%2,%3}, [%4];" \
        : "=r"((r)[0]), "=r"((r)[1]), "=r"((r)[2]), "=r"((r)[3]) : "r"(addr))

// ================= fused kernel: conv -> YS(smem) -> double GEMM -> out ======
// CTA: 512 threads, 16x32 (h,w) tile, 8 z-slices, rolling 3-plane window.
#define TY 16
#define TX 32
#define TZ 8
#define XROW 35                   // 34 used + 1 pad
#define XS_PLANE (18 * XROW)      // 630
#define XS_CH    (3 * XS_PLANE)   // 1890
#define XS_BYTES (16 * XS_CH * 4) // 120960
#define YS_BYTES (512 * 128)      // 65536
#define F_SMEM_BYTES (XS_BYTES + YS_BYTES + 16384 + 4096 + 512)

__device__ __forceinline__ void load_plane(float* XS, const float* __restrict__ x,
                                           int b, int zp, int ty0, int tx0,
                                           int slot, int tid) {
    const bool zin = (zp >= 0 && zp < SS);
    for (int i = tid; i < 18 * 34; i += 512) {
        int hy = i / 34;
        int wx = i % 34;
        int dst = slot * XS_PLANE + hy * XROW + wx;
        int gy2 = hy - 1 + ty0, gx2 = wx - 1 + tx0;
        if (zin && gy2 >= 0 && gy2 < SS && gx2 >= 0 && gx2 < SS) {
            const float4* p = (const float4*)(x + ((((size_t)b * SS + zp) * SS + gy2) * SS + gx2) * SC);
#pragma unroll
            for (int q = 0; q < 4; q++) {
                float4 v = p[q];
                XS[(4 * q + 0) * XS_CH + dst] = v.x;
                XS[(4 * q + 1) * XS_CH + dst] = v.y;
                XS[(4 * q + 2) * XS_CH + dst] = v.z;
                XS[(4 * q + 3) * XS_CH + dst] = v.w;
            }
        } else {
#pragma unroll
            for (int c = 0; c < 16; c++) XS[c * XS_CH + dst] = 0.f;
        }
    }
}

__global__ __launch_bounds__(512, 1)
void nca_fused(const float* __restrict__ x, const float* __restrict__ w0g,
               const float* __restrict__ w1g, const float* __restrict__ b0,
               const float* __restrict__ stoch, float* __restrict__ out) {
    extern __shared__ float SM[];
    float*   XS  = SM;
    uint8_t* YS  = (uint8_t*)(SM + 16 * XS_CH);
    uint2*   W0F = (uint2*)(YS + YS_BYTES);
    uint2*   W1F = W0F + 64 * 32;
    float*   B0S = (float*)(W1F + 16 * 32);

    const int tid = threadIdx.x;

    // build mma b-fragments in smem directly from w0/w1 (K-permuted, scaled)
    {
        for (int t = tid; t < 64 * 32; t += 512) {
            int f = t >> 5;
            int kt = f >> 4, nt = f & 15;
            int n = nt * 8 + ((t & 31) >> 2);
            int tgq = (t & 31) & 3;
            int kb = kt * 16 + 2 * tgq;
            float e[4];
#pragma unroll
            for (int q = 0; q < 4; q++) {
                int kp = kb + (q >> 1) * 8 + (q & 1);
                int ko = (kp & 3) * 16 + (kp >> 2);
                float s = (ko >= 16) ? (1.f / 32.f) : 1.f;
                e[q] = w0g[n * 64 + ko] * s;
            }
            uint2 v;
            v.x = pack_bf16x2(e[0], e[1]);
            v.y = pack_bf16x2(e[2], e[3]);
            W0F[t] = v;
        }
        for (int t = tid; t < 16 * 32; t += 512) {
            int f = t >> 5;
            int kt = f >> 1, nt = f & 1;
            int n = nt * 8 + ((t & 31) >> 2);
            int tgq = (t & 31) & 3;
            int kb = kt * 16 + 2 * tgq;
            uint2 v;
            v.x = pack_bf16x2(w1g[n * 128 + kb],     w1g[n * 128 + kb + 1]);
            v.y = pack_bf16x2(w1g[n * 128 + kb + 8], w1g[n * 128 + kb + 9]);
            W1F[t] = v;
        }
        if (tid < 128) B0S[tid] = b0[tid];
    }

    const int b   = blockIdx.z >> 3;
    const int z0  = (blockIdx.z & 7) * TZ;
    const int ty0 = blockIdx.y * TY;
    const int tx0 = blockIdx.x * TX;

    // fill the full 3-plane window up front
    load_plane(XS, x, b, z0 - 1, ty0, tx0, ((z0 - 1) + 3) % 3, tid);
    load_plane(XS, x, b, z0,     ty0, tx0, z0 % 3,             tid);
    load_plane(XS, x, b, z0 + 1, ty0, tx0, (z0 + 1) % 3,       tid);

    // conv mapping: cg(4 channels) x ly(16) x tx4(8 groups of 4 x-voxels)
    const int cg  = tid >> 7;
    const int sub = tid & 127;
    const int ly  = sub >> 3;
    const int tx4 = sub & 7;
    const int gh  = ty0 + ly;
    const int gx0 = tx0 + 4 * tx4;

    // gemm mapping
    const int w    = tid >> 5;
    const int lane = tid & 31;
    const int g    = lane >> 2;
    const int tg   = lane & 3;

    __syncthreads();

    for (int z = z0; z < z0 + TZ; z++) {
        const int s0 = ((z - 1) + 3) % 3, s1 = z % 3, s2 = (z + 1) % 3;
        const size_t voxbase = (((size_t)b * SS + z) * SS + gh) * SS + gx0;
        const int lrow0 = ly * TX + 4 * tx4;

        // ---------------- conv phase: y' -> YS ----------------
#pragma unroll
        for (int cpair = 0; cpair < 2; cpair++) {
            float st[2][4][4];
#pragma unroll
            for (int ci = 0; ci < 2; ci++) {
                const int c = cg * 4 + cpair * 2 + ci;
                const float* base = XS + c * XS_CH;

                float a[3][6], d[3][6], ctrv[4], cm[6];
#pragma unroll
                for (int dy = 0; dy < 3; dy++) {
#pragma unroll
                    for (int j = 0; j < 6; j++) {
                        int idx = (ly + dy) * XROW + 4 * tx4 + j;
                        float vm = base[s0 * XS_PLANE + idx];
                        float vc = base[s1 * XS_PLANE + idx];
                        float vp = base[s2 * XS_PLANE + idx];
                        a[dy][j] = fmaf(2.f, vc, vm) + vp;
                        d[dy][j] = vp - vm;
                        if (c == 3) {
                            float m = fmaxf(fmaxf(vm, vc), vp);
                            cm[j] = (dy == 0) ? m : fmaxf(cm[j], m);
                        }
                        if (dy == 1 && j >= 1 && j <= 4) ctrv[j - 1] = vc;
                    }
                }
#pragma unroll
                for (int v = 0; v < 4; v++) {
                    float gx = (a[0][v + 2] - a[0][v])
                             + 2.f * (a[1][v + 2] - a[1][v])
                             + (a[2][v + 2] - a[2][v]);
                    float sx0 = fmaf(2.f, a[0][v + 1], a[0][v]) + a[0][v + 2];
                    float sx2 = fmaf(2.f, a[2][v + 1], a[2][v]) + a[2][v + 2];
                    float gy = sx2 - sx0;
                    float t0 = fmaf(2.f, d[0][v + 1], d[0][v]) + d[0][v + 2];
                    float t1 = fmaf(2.f, d[1][v + 1], d[1][v]) + d[1][v + 2];
                    float t2 = fmaf(2.f, d[2][v + 1], d[2][v]) + d[2][v + 2];
                    float gz = fmaf(2.f, t1, t0) + t2;
                    st[ci][v][0] = ctrv[v];
                    st[ci][v][1] = gx;
                    st[ci][v][2] = gy;
                    st[ci][v][3] = gz;
                }
                if (c == 3) {
                    uchar4 pre;
                    pre.x = (fmaxf(fmaxf(cm[0], cm[1]), cm[2]) > 0.1f) ? 1 : 0;
                    pre.y = (fmaxf(fmaxf(cm[1], cm[2]), cm[3]) > 0.1f) ? 1 : 0;
                    pre.z = (fmaxf(fmaxf(cm[2], cm[3]), cm[4]) > 0.1f) ? 1 : 0;
                    pre.w = (fmaxf(fmaxf(cm[3], cm[4]), cm[5]) > 0.1f) ? 1 : 0;
                    *(uchar4*)(g_pre + voxbase) = pre;
                }
            }
            const int c16 = cg * 2 + cpair;
#pragma unroll
            for (int v = 0; v < 4; v++) {
                int row = lrow0 + v;
                uint4 o;
                o.x = pack_bf16x2(st[0][v][0], st[0][v][1]);
                o.y = pack_bf16x2(st[0][v][2], st[0][v][3]);
                o.z = pack_bf16x2(st[1][v][0], st[1][v][1]);
                o.w = pack_bf16x2(st[1][v][2], st[1][v][3]);
                *(uint4*)(YS + row * 128 + ((c16 ^ (row & 7)) << 4)) = o;
            }
        }
        __syncthreads();   // YS ready; conv reads of slot (z-1)%3 complete

        // -------- prefetch plane z+2 (overwrites slot (z-1)%3); latency hides
        //          behind the GEMM phase below, completion enforced by the
        //          loop-end barrier ------------------------------------------
        if (z + 2 <= z0 + TZ)
            load_plane(XS, x, b, z + 2, ty0, tx0, (z + 2) % 3, tid);

        // ---------------- GEMM phase ----------------
        uint32_t A[2][4][4];
#pragma unroll
        for (int mt = 0; mt < 2; mt++) {
#pragma unroll
            for (int kt = 0; kt < 4; kt++) {
                int r   = w * 32 + mt * 16 + (lane & 15);
                int c16 = kt * 2 + (lane >> 4);
                uint32_t addr = smem_u32(YS) + r * 128 + ((c16 ^ (r & 7)) << 4);
                LDMATRIX_X4(A[mt][kt], addr);
            }
        }

        float dxacc[2][2][4];
#pragma unroll
        for (int i = 0; i < 16; i++) ((float*)dxacc)[i] = 0.f;

#pragma unroll
        for (int nc = 0; nc < 4; nc++) {
            float hc[2][4][4];
#pragma unroll
            for (int i = 0; i < 32; i++) ((float*)hc)[i] = 0.f;

#pragma unroll
            for (int kt = 0; kt < 4; kt++) {
#pragma unroll
                for (int n8 = 0; n8 < 4; n8++) {
                    uint2 bb = W0F[(kt * 16 + nc * 4 + n8) * 32 + lane];
                    mma_bf16(hc[0][n8], A[0][kt], bb);
                    mma_bf16(hc[1][n8], A[1][kt], bb);
                }
            }

            uint32_t a2[2][2][4];
#pragma unroll
            for (int n8 = 0; n8 < 4; n8++) {
                float2 bb = *(const float2*)(B0S + nc * 32 + n8 * 8 + 2 * tg);
                int kt2 = n8 >> 1, half = n8 & 1;
#pragma unroll
                for (int mt = 0; mt < 2; mt++) {
                    float f0 = fmaxf(hc[mt][n8][0] + bb.x, 0.f);
                    float f1 = fmaxf(hc[mt][n8][1] + bb.y, 0.f);
                    float f2 = fmaxf(hc[mt][n8][2] + bb.x, 0.f);
                    float f3 = fmaxf(hc[mt][n8][3] + bb.y, 0.f);
                    a2[mt][kt2][half * 2 + 0] = pack_bf16x2(f0, f1);
                    a2[mt][kt2][half * 2 + 1] = pack_bf16x2(f2, f3);
                }
            }

#pragma unroll
            for (int kt2 = 0; kt2 < 2; kt2++) {
#pragma unroll
                for (int n8o = 0; n8o < 2; n8o++) {
                    uint2 b2 = W1F[((nc * 2 + kt2) * 2 + n8o) * 32 + lane];
                    mma_bf16(dxacc[0][n8o], a2[0][kt2], b2);
                    mma_bf16(dxacc[1][n8o], a2[1][kt2], b2);
                }
            }
        }

        // ------------- epilogue: out = x + dx*mask (x from XS smem) ----------
#pragma unroll
        for (int mt = 0; mt < 2; mt++) {
#pragma unroll
            for (int vv = 0; vv < 2; vv++) {
                int lv = w * 32 + mt * 16 + g + vv * 8;
                int y_l = lv >> 5, x_l = lv & 31;
                size_t gvox = (((size_t)b * SS + z) * SS + ty0 + y_l) * SS + tx0 + x_l;
                float m = (stoch[gvox] > 0.5f) ? 1.f : 0.f;
                const int xsi = s1 * XS_PLANE + (y_l + 1) * XROW + (x_l + 1);
#pragma unroll
                for (int n8o = 0; n8o < 2; n8o++) {
                    int c = n8o * 8 + 2 * tg;
                    float2 xv;
                    xv.x = XS[(c + 0) * XS_CH + xsi];
                    xv.y = XS[(c + 1) * XS_CH + xsi];
                    xv.x += dxacc[mt][n8o][vv * 2 + 0] * m;
                    xv.y += dxacc[mt][n8o][vv * 2 + 1] * m;
                    *(float2*)(out + gvox * 16 + c) = xv;
                    if (n8o == 0 && tg == 1) g_alpha[gvox] = xv.y;
                }
            }
        }
        __syncthreads();   // prefetch complete; YS/XS reads done
    }
}

// ================= kill pass: zero voxels where life == 0 (4-wide) ===========
__global__ __launch_bounds__(256)
void nca_kill(float* __restrict__ out) {
    const int t = blockIdx.x * 256 + threadIdx.x;   // 0..262143
    const int b  = t >> 16;
    const int r  = t & 65535;
    const int d  = r >> 10;
    const int h  = (r >> 4) & 63;
    const int w4 = (r & 15) << 2;                   // 0,4,...,60
    const int v0 = ((b * SS + d) * SS + h) * SS + w4;

    const uint32_t pv = *(const uint32_t*)(g_pre + v0);

    float cm[6];
#pragma unroll
    for (int j = 0; j < 6; j++) cm[j] = -1e30f;

    if (pv != 0) {
        const int jlo = (w4 == 0) ? 1 : 0;
        const int jhi = (w4 == 60) ? 4 : 5;
#pragma unroll
        for (int dz = -1; dz <= 1; dz++) {
            int dd = d + dz;
            if (dd < 0 || dd >= SS) continue;
#pragma unroll
            for (int dy = -1; dy <= 1; dy++) {
                int hh = h + dy;
                if (hh < 0 || hh >= SS) continue;
                const float* row = g_alpha + ((b * SS + dd) * SS + hh) * SS + (w4 - 1);
                for (int j = jlo; j <= jhi; j++)
                    cm[j] = fmaxf(cm[j], row[j]);
            }
        }
    }

#pragma unroll
    for (int i = 0; i < 4; i++) {
        bool life = (((pv >> (8 * i)) & 255u) != 0u) &&
                    (fmaxf(fmaxf(cm[i], cm[i + 1]), cm[i + 2]) > 0.1f);
        if (!life) {
            float4 zz = make_float4(0.f, 0.f, 0.f, 0.f);
            float4* o = (float4*)out + (size_t)(v0 + i) * 4;
#pragma unroll
            for (int q = 0; q < 4; q++) o[q] = zz;
        }
    }
}

extern "C" void kernel_launch(void* const* d_in, const int* in_sizes, int n_in,
                              void* d_out, int out_size) {
    const float* x     = (const float*)d_in[0];
    const float* w0    = (const float*)d_in[1];
    const float* b0    = (const float*)d_in[2];
    const float* w1    = (const float*)d_in[3];
    const float* stoch = (const float*)d_in[4];

    cudaFuncSetAttribute(nca_fused, cudaFuncAttributeMaxDynamicSharedMemorySize, F_SMEM_BYTES);
    dim3 gridF(SS / TX, SS / TY, SB * (SS / TZ));   // (2, 4, 32)
    nca_fused<<<gridF, 512, F_SMEM_BYTES>>>(x, w0, w1, b0, stoch, (float*)d_out);

    nca_kill<<<NVOX / 4 / 256, 256>>>((float*)d_out);
}

// round 9
// speedup vs baseline: 5.3491x; 1.0721x over previous
#include <cuda_runtime.h>
#include <cuda_bf16.h>
#include <cstdint>

// NCA 3D update step — fused conv+GEMM (bf16 HMMA) writing x2 directly to out;
// single kill pass (4-wide, fully unrolled) zeroes dead voxels.
//   x:[4,64,64,64,16] f32, w0:[128,64], b0:[128], w1:[16,128], stoch:[4,64^3,1]
// out = (x + dx*(stoch>0.5)) * (pre_life & alive(x2))
// y is K-PERMUTED in YS smem: y'[4c+s] = {x_c, gx_c, gy_c, gz_c}; 1/32 folded into W0.

#define SB 4
#define SS 64
#define SC 16
#define NVOX (SB * SS * SS * SS)

// ---------------- device scratch ----------------
__device__ float         g_alpha_buf[NVOX + 32];     // padded: safe w-1/w+4 reads
#define G_ALPHA (g_alpha_buf + 16)
__device__ unsigned char g_pre[NVOX];                // 1 MB

__device__ __forceinline__ uint32_t smem_u32(const void* p) {
    uint32_t a;
    asm("{ .reg .u64 t; cvta.to.shared.u64 t, %1; cvt.u32.u64 %0, t; }" : "=r"(a) : "l"(p));
    return a;
}
__device__ __forceinline__ uint32_t pack_bf16x2(float lo, float hi) {
    uint32_t r;
    asm("cvt.rn.bf16x2.f32 %0, %1, %2;" : "=r"(r) : "f"(hi), "f"(lo));
    return r;
}
__device__ __forceinline__ void mma_bf16(float* c, const uint32_t* a, const uint2 b) {
    asm volatile(
        "mma.sync.aligned.m16n8k16.row.col.f32.bf16.bf16.f32 "
        "{%0,%1,%2,%3}, {%4,%5,%6,%7}, {%8,%9}, {%0,%1,%2,%3};"
        : "+f"(c[0]), "+f"(c[1]), "+f"(c[2]), "+f"(c[3])
        : "r"(a[0]), "r"(a[1]), "r"(a[2]), "r"(a[3]), "r"(b.x), "r"(b.y));
}
#define LDMATRIX_X4(r, addr)                                                   \
    asm volatile("ldmatrix.sync.aligned.m8n8.x4.shared.b16 {%0,%1,%2,%3}, [%4];" \
        : "=r"((r)[0]), "=r"((r)[1]), "=r"((r)[2]), "=r"((r)[3]) : "r"(addr))

// ================= fused kernel: conv -> YS(smem) -> double GEMM -> out ======
// CTA: 512 threads, 16x32 (h,w) tile, 8 z-slices, rolling 3-plane window.
#define TY 16
#define TX 32
#define TZ 8
#define XROW 34                   // EVEN: enables 8B-aligned ld.shared.v2.f32
#define XS_PLANE (18 * XROW)      // 612
#define XS_CH    (3 * XS_PLANE)   // 1836
#define XS_BYTES (16 * XS_CH * 4) // 117504
#define YS_BYTES (512 * 128)      // 65536
#define F_SMEM_BYTES (XS_BYTES + YS_BYTES + 16384 + 4096 + 512)

__device__ __forceinline__ void load_plane(float* XS, const float* __restrict__ x,
                                           int b, int zp, int ty0, int tx0,
                                           int slot, int tid) {
    const bool zin = (zp >= 0 && zp < SS);
    for (int i = tid; i < 18 * 34; i += 512) {
        int hy = i / 34;
        int wx = i % 34;
        int dst = slot * XS_PLANE + hy * XROW + wx;
        int gy2 = hy - 1 + ty0, gx2 = wx - 1 + tx0;
        if (zin && gy2 >= 0 && gy2 < SS && gx2 >= 0 && gx2 < SS) {
            const float4* p = (const float4*)(x + ((((size_t)b * SS + zp) * SS + gy2) * SS + gx2) * SC);
#pragma unroll
            for (int q = 0; q < 4; q++) {
                float4 v = p[q];
                XS[(4 * q + 0) * XS_CH + dst] = v.x;
                XS[(4 * q + 1) * XS_CH + dst] = v.y;
                XS[(4 * q + 2) * XS_CH + dst] = v.z;
                XS[(4 * q + 3) * XS_CH + dst] = v.w;
            }
        } else {
#pragma unroll
            for (int c = 0; c < 16; c++) XS[c * XS_CH + dst] = 0.f;
        }
    }
}

__global__ __launch_bounds__(512, 1)
void nca_fused(const float* __restrict__ x, const float* __restrict__ w0g,
               const float* __restrict__ w1g, const float* __restrict__ b0,
               const float* __restrict__ stoch, float* __restrict__ out) {
    extern __shared__ float SM[];
    float*   XS  = SM;
    uint8_t* YS  = (uint8_t*)(SM + 16 * XS_CH);
    uint2*   W0F = (uint2*)(YS + YS_BYTES);
    uint2*   W1F = W0F + 64 * 32;
    float*   B0S = (float*)(W1F + 16 * 32);

    const int tid = threadIdx.x;

    // build mma b-fragments in smem directly from w0/w1 (K-permuted, scaled)
    {
        for (int t = tid; t < 64 * 32; t += 512) {
            int f = t >> 5;
            int kt = f >> 4, nt = f & 15;
            int n = nt * 8 + ((t & 31) >> 2);
            int tgq = (t & 31) & 3;
            int kb = kt * 16 + 2 * tgq;
            float e[4];
#pragma unroll
            for (int q = 0; q < 4; q++) {
                int kp = kb + (q >> 1) * 8 + (q & 1);
                int ko = (kp & 3) * 16 + (kp >> 2);
                float s = (ko >= 16) ? (1.f / 32.f) : 1.f;
                e[q] = w0g[n * 64 + ko] * s;
            }
            uint2 v;
            v.x = pack_bf16x2(e[0], e[1]);
            v.y = pack_bf16x2(e[2], e[3]);
            W0F[t] = v;
        }
        for (int t = tid; t < 16 * 32; t += 512) {
            int f = t >> 5;
            int kt = f >> 1, nt = f & 1;
            int n = nt * 8 + ((t & 31) >> 2);
            int tgq = (t & 31) & 3;
            int kb = kt * 16 + 2 * tgq;
            uint2 v;
            v.x = pack_bf16x2(w1g[n * 128 + kb],     w1g[n * 128 + kb + 1]);
            v.y = pack_bf16x2(w1g[n * 128 + kb + 8], w1g[n * 128 + kb + 9]);
            W1F[t] = v;
        }
        if (tid < 128) B0S[tid] = b0[tid];
    }

    const int b   = blockIdx.z >> 3;
    const int z0  = (blockIdx.z & 7) * TZ;
    const int ty0 = blockIdx.y * TY;
    const int tx0 = blockIdx.x * TX;

    // fill the full 3-plane window up front
    load_plane(XS, x, b, z0 - 1, ty0, tx0, ((z0 - 1) + 3) % 3, tid);
    load_plane(XS, x, b, z0,     ty0, tx0, z0 % 3,             tid);
    load_plane(XS, x, b, z0 + 1, ty0, tx0, (z0 + 1) % 3,       tid);

    // conv mapping: cg(4 channels) x ly(16) x tx4(8 groups of 4 x-voxels)
    const int cg  = tid >> 7;
    const int sub = tid & 127;
    const int ly  = sub >> 3;
    const int tx4 = sub & 7;
    const int gh  = ty0 + ly;
    const int gx0 = tx0 + 4 * tx4;

    // gemm mapping
    const int w    = tid >> 5;
    const int lane = tid & 31;
    const int g    = lane >> 2;
    const int tg   = lane & 3;

    __syncthreads();

    for (int z = z0; z < z0 + TZ; z++) {
        const int s0 = ((z - 1) + 3) % 3, s1 = z % 3, s2 = (z + 1) % 3;
        const size_t voxbase = (((size_t)b * SS + z) * SS + gh) * SS + gx0;
        const int lrow0 = ly * TX + 4 * tx4;

        // ---------------- conv phase: y' -> YS ----------------
#pragma unroll
        for (int cpair = 0; cpair < 2; cpair++) {
            float st[2][4][4];
#pragma unroll
            for (int ci = 0; ci < 2; ci++) {
                const int c = cg * 4 + cpair * 2 + ci;
                const float* base = XS + c * XS_CH;

                float a[3][6], d[3][6], ctrv[4], cm[6];
#pragma unroll
                for (int dy = 0; dy < 3; dy++) {
#pragma unroll
                    for (int jp = 0; jp < 3; jp++) {       // float2 pairs j=2jp,2jp+1
                        int idx = (ly + dy) * XROW + 4 * tx4 + 2 * jp;
                        float2 vm = *(const float2*)(base + s0 * XS_PLANE + idx);
                        float2 vc = *(const float2*)(base + s1 * XS_PLANE + idx);
                        float2 vp = *(const float2*)(base + s2 * XS_PLANE + idx);
                        a[dy][2 * jp]     = fmaf(2.f, vc.x, vm.x) + vp.x;
                        a[dy][2 * jp + 1] = fmaf(2.f, vc.y, vm.y) + vp.y;
                        d[dy][2 * jp]     = vp.x - vm.x;
                        d[dy][2 * jp + 1] = vp.y - vm.y;
                        if (c == 3) {
                            float m0 = fmaxf(fmaxf(vm.x, vc.x), vp.x);
                            float m1 = fmaxf(fmaxf(vm.y, vc.y), vp.y);
                            if (dy == 0) { cm[2 * jp] = m0; cm[2 * jp + 1] = m1; }
                            else { cm[2 * jp] = fmaxf(cm[2 * jp], m0);
                                   cm[2 * jp + 1] = fmaxf(cm[2 * jp + 1], m1); }
                        }
                        if (dy == 1) {
                            if (jp == 0) ctrv[0] = vc.y;
                            if (jp == 1) { ctrv[1] = vc.x; ctrv[2] = vc.y; }
                            if (jp == 2) ctrv[3] = vc.x;
                        }
                    }
                }
#pragma unroll
                for (int v = 0; v < 4; v++) {
                    float gx = (a[0][v + 2] - a[0][v])
                             + 2.f * (a[1][v + 2] - a[1][v])
                             + (a[2][v + 2] - a[2][v]);
                    float sx0 = fmaf(2.f, a[0][v + 1], a[0][v]) + a[0][v + 2];
                    float sx2 = fmaf(2.f, a[2][v + 1], a[2][v]) + a[2][v + 2];
                    float gy = sx2 - sx0;
                    float t0 = fmaf(2.f, d[0][v + 1], d[0][v]) + d[0][v + 2];
                    float t1 = fmaf(2.f, d[1][v + 1], d[1][v]) + d[1][v + 2];
                    float t2 = fmaf(2.f, d[2][v + 1], d[2][v]) + d[2][v + 2];
                    float gz = fmaf(2.f, t1, t0) + t2;
                    st[ci][v][0] = ctrv[v];
                    st[ci][v][1] = gx;
                    st[ci][v][2] = gy;
                    st[ci][v][3] = gz;
                }
                if (c == 3) {
                    uchar4 pre;
                    pre.x = (fmaxf(fmaxf(cm[0], cm[1]), cm[2]) > 0.1f) ? 1 : 0;
                    pre.y = (fmaxf(fmaxf(cm[1], cm[2]), cm[3]) > 0.1f) ? 1 : 0;
                    pre.z = (fmaxf(fmaxf(cm[2], cm[3]), cm[4]) > 0.1f) ? 1 : 0;
                    pre.w = (fmaxf(fmaxf(cm[3], cm[4]), cm[5]) > 0.1f) ? 1 : 0;
                    *(uchar4*)(g_pre + voxbase) = pre;
                }
            }
            const int c16 = cg * 2 + cpair;
#pragma unroll
            for (int v = 0; v < 4; v++) {
                int row = lrow0 + v;
                uint4 o;
                o.x = pack_bf16x2(st[0][v][0], st[0][v][1]);
                o.y = pack_bf16x2(st[0][v][2], st[0][v][3]);
                o.z = pack_bf16x2(st[1][v][0], st[1][v][1]);
                o.w = pack_bf16x2(st[1][v][2], st[1][v][3]);
                *(uint4*)(YS + row * 128 + ((c16 ^ (row & 7)) << 4)) = o;
            }
        }
        __syncthreads();   // YS ready; conv reads of slot (z-1)%3 complete

        // -------- prefetch stoch for epilogue (consumed after GEMM) ----------
        float mvals[4];
#pragma unroll
        for (int mt = 0; mt < 2; mt++)
#pragma unroll
            for (int vv = 0; vv < 2; vv++) {
                int lv = w * 32 + mt * 16 + g + vv * 8;
                size_t gvox = (((size_t)b * SS + z) * SS + ty0 + (lv >> 5)) * SS + tx0 + (lv & 31);
                mvals[mt * 2 + vv] = stoch[gvox];
            }

        // -------- prefetch plane z+2 (overwrites slot (z-1)%3); latency hides
        //          behind the GEMM phase below ------------------------------
        if (z + 2 <= z0 + TZ)
            load_plane(XS, x, b, z + 2, ty0, tx0, (z + 2) % 3, tid);

        // ---------------- GEMM phase ----------------
        uint32_t A[2][4][4];
#pragma unroll
        for (int mt = 0; mt < 2; mt++) {
#pragma unroll
            for (int kt = 0; kt < 4; kt++) {
                int r   = w * 32 + mt * 16 + (lane & 15);
                int c16 = kt * 2 + (lane >> 4);
                uint32_t addr = smem_u32(YS) + r * 128 + ((c16 ^ (r & 7)) << 4);
                LDMATRIX_X4(A[mt][kt], addr);
            }
        }

        float dxacc[2][2][4];
#pragma unroll
        for (int i = 0; i < 16; i++) ((float*)dxacc)[i] = 0.f;

#pragma unroll
        for (int nc = 0; nc < 4; nc++) {
            float hc[2][4][4];
#pragma unroll
            for (int i = 0; i < 32; i++) ((float*)hc)[i] = 0.f;

#pragma unroll
            for (int kt = 0; kt < 4; kt++) {
#pragma unroll
                for (int n8 = 0; n8 < 4; n8++) {
                    uint2 bb = W0F[(kt * 16 + nc * 4 + n8) * 32 + lane];
                    mma_bf16(hc[0][n8], A[0][kt], bb);
                    mma_bf16(hc[1][n8], A[1][kt], bb);
                }
            }

            uint32_t a2[2][2][4];
#pragma unroll
            for (int n8 = 0; n8 < 4; n8++) {
                float2 bb = *(const float2*)(B0S + nc * 32 + n8 * 8 + 2 * tg);
                int kt2 = n8 >> 1, half = n8 & 1;
#pragma unroll
                for (int mt = 0; mt < 2; mt++) {
                    float f0 = fmaxf(hc[mt][n8][0] + bb.x, 0.f);
                    float f1 = fmaxf(hc[mt][n8][1] + bb.y, 0.f);
                    float f2 = fmaxf(hc[mt][n8][2] + bb.x, 0.f);
                    float f3 = fmaxf(hc[mt][n8][3] + bb.y, 0.f);
                    a2[mt][kt2][half * 2 + 0] = pack_bf16x2(f0, f1);
                    a2[mt][kt2][half * 2 + 1] = pack_bf16x2(f2, f3);
                }
            }

#pragma unroll
            for (int kt2 = 0; kt2 < 2; kt2++) {
#pragma unroll
                for (int n8o = 0; n8o < 2; n8o++) {
                    uint2 b2 = W1F[((nc * 2 + kt2) * 2 + n8o) * 32 + lane];
                    mma_bf16(dxacc[0][n8o], a2[0][kt2], b2);
                    mma_bf16(dxacc[1][n8o], a2[1][kt2], b2);
                }
            }
        }

        // ------------- epilogue: out = x + dx*mask (x from XS smem) ----------
#pragma unroll
        for (int mt = 0; mt < 2; mt++) {
#pragma unroll
            for (int vv = 0; vv < 2; vv++) {
                int lv = w * 32 + mt * 16 + g + vv * 8;
                int y_l = lv >> 5, x_l = lv & 31;
                size_t gvox = (((size_t)b * SS + z) * SS + ty0 + y_l) * SS + tx0 + x_l;
                float m = (mvals[mt * 2 + vv] > 0.5f) ? 1.f : 0.f;
                const int xsi = s1 * XS_PLANE + (y_l + 1) * XROW + (x_l + 1);
#pragma unroll
                for (int n8o = 0; n8o < 2; n8o++) {
                    int c = n8o * 8 + 2 * tg;
                    float2 xv;
                    xv.x = XS[(c + 0) * XS_CH + xsi];
                    xv.y = XS[(c + 1) * XS_CH + xsi];
                    xv.x += dxacc[mt][n8o][vv * 2 + 0] * m;
                    xv.y += dxacc[mt][n8o][vv * 2 + 1] * m;
                    *(float2*)(out + gvox * 16 + c) = xv;
                    if (n8o == 0 && tg == 1) G_ALPHA[gvox] = xv.y;
                }
            }
        }
        __syncthreads();   // prefetch complete; YS/XS reads done
    }
}

// ================= kill pass: zero voxels where life == 0 (4-wide) ===========
__global__ __launch_bounds__(256)
void nca_kill(float* __restrict__ out) {
    const int t = blockIdx.x * 256 + threadIdx.x;   // 0..262143
    const int b  = t >> 16;
    const int r  = t & 65535;
    const int d  = r >> 10;
    const int h  = (r >> 4) & 63;
    const int w4 = (r & 15) << 2;                   // 0,4,...,60
    const int v0 = ((b * SS + d) * SS + h) * SS + w4;

    const uint32_t pv = *(const uint32_t*)(g_pre + v0);

    float cm[6];
#pragma unroll
    for (int j = 0; j < 6; j++) cm[j] = -1e30f;

    if (pv != 0) {
#pragma unroll
        for (int dz = -1; dz <= 1; dz++) {
            int dd = d + dz;
            if (dd < 0 || dd >= SS) continue;
#pragma unroll
            for (int dy = -1; dy <= 1; dy++) {
                int hh = h + dy;
                if (hh < 0 || hh >= SS) continue;
                const float* row = G_ALPHA + ((b * SS + dd) * SS + hh) * SS + (w4 - 1);
#pragma unroll
                for (int j = 0; j < 6; j++)       // compile-time bounds: unrolls
                    cm[j] = fmaxf(cm[j], row[j]); // padded buffer: always safe
            }
        }
        if (w4 == 0)  cm[0] = -1e30f;   // w=-1 column invalid at left edge
        if (w4 == 60) cm[5] = -1e30f;   // w=64 column invalid at right edge
    }

#pragma unroll
    for (int i = 0; i < 4; i++) {
        bool life = (((pv >> (8 * i)) & 255u) != 0u) &&
                    (fmaxf(fmaxf(cm[i], cm[i + 1]), cm[i + 2]) > 0.1f);
        if (!life) {
            float4 zz = make_float4(0.f, 0.f, 0.f, 0.f);
            float4* o = (float4*)out + (size_t)(v0 + i) * 4;
#pragma unroll
            for (int q = 0; q < 4; q++) o[q] = zz;
        }
    }
}

extern "C" void kernel_launch(void* const* d_in, const int* in_sizes, int n_in,
                              void* d_out, int out_size) {
    const float* x     = (const float*)d_in[0];
    const float* w0    = (const float*)d_in[1];
    const float* b0    = (const float*)d_in[2];
    const float* w1    = (const float*)d_in[3];
    const float* stoch = (const float*)d_in[4];

    cudaFuncSetAttribute(nca_fused, cudaFuncAttributeMaxDynamicSharedMemorySize, F_SMEM_BYTES);
    dim3 gridF(SS / TX, SS / TY, SB * (SS / TZ));   // (2, 4, 32)
    nca_fused<<<gridF, 512, F_SMEM_BYTES>>>(x, w0, w1, b0, stoch, (float*)d_out);

    nca_kill<<<NVOX / 4 / 256, 256>>>((float*)d_out);
}